// round 3
// baseline (speedup 1.0000x reference)
#include <cuda_runtime.h>

#define NB 4
#define NT 1024
#define ND 512
#define NH 8
#define NHD 64
#define NHDIM 512   // NH*NHD

// ---------------- scratch (static device arrays; no allocation) ----------------
__device__ float g_q [NB*NH*NT*NHD];                 // [b,h,t,d]   8 MB
__device__ float g_k [NB*NH*NT*NHD];
__device__ float g_v [NB*NH*NT*NHD];
__device__ float g_At[(size_t)NB*NH*NT*NT];          // [b,h,q,k] 128 MB (softmaxed)
__device__ float g_Rf[(size_t)NB*NT*NT];             // [b,q,k]    16 MB
__device__ float g_invf[NB*NH*NT];                   // 1/denominator per row
__device__ float g_invr[NB*NH*NT];
__device__ float g_Tf[NB*NT*NHDIM];                  // [b,t, h*64+d]  8 MB
__device__ float g_Tr[NB*NT*NHDIM];

// ---------------- K1: projection GEMM, C = X@W + b, permuted to [b,h,t,d] -----
template<int SEL>
__global__ __launch_bounds__(256) void k_proj(const float* __restrict__ X,
                                              const float* __restrict__ W,
                                              const float* __restrict__ bias)
{
    __shared__ float sA[64][16];
    __shared__ float sB[16][64];
    const int tid = threadIdx.x;
    const int m0 = blockIdx.y*64, n0 = blockIdx.x*64;
    const int ty = tid>>4, tx = tid&15;
    float acc[4][4];
#pragma unroll
    for (int i=0;i<4;i++)
#pragma unroll
        for (int j=0;j<4;j++) acc[i][j]=0.f;

    for (int ko=0; ko<ND; ko+=16){
        {
            int r = tid>>2, c4 = tid&3;
            *(float4*)&sA[r][c4*4] = *(const float4*)&X[(size_t)(m0+r)*ND + ko + c4*4];
        }
        {
            int r = tid>>4, c = tid&15;
            *(float4*)&sB[r][c*4] = *(const float4*)&W[(size_t)(ko+r)*NHDIM + n0 + c*4];
        }
        __syncthreads();
#pragma unroll
        for (int kk=0;kk<16;kk++){
            float a0=sA[ty*4+0][kk], a1=sA[ty*4+1][kk];
            float a2=sA[ty*4+2][kk], a3=sA[ty*4+3][kk];
            float4 bv = *(float4*)&sB[kk][tx*4];
            acc[0][0]+=a0*bv.x; acc[0][1]+=a0*bv.y; acc[0][2]+=a0*bv.z; acc[0][3]+=a0*bv.w;
            acc[1][0]+=a1*bv.x; acc[1][1]+=a1*bv.y; acc[1][2]+=a1*bv.z; acc[1][3]+=a1*bv.w;
            acc[2][0]+=a2*bv.x; acc[2][1]+=a2*bv.y; acc[2][2]+=a2*bv.z; acc[2][3]+=a2*bv.w;
            acc[3][0]+=a3*bv.x; acc[3][1]+=a3*bv.y; acc[3][2]+=a3*bv.z; acc[3][3]+=a3*bv.w;
        }
        __syncthreads();
    }
    float* dst = (SEL==0)?g_q:(SEL==1)?g_k:g_v;
#pragma unroll
    for (int i=0;i<4;i++){
        int m = m0+ty*4+i;
        int b = m>>10, t = m&1023;
#pragma unroll
        for (int j=0;j<4;j++){
            int n = n0+tx*4+j;
            int h = n>>6, d = n&63;
            dst[(((size_t)(b*NH+h)*NT)+t)*NHD + d] = acc[i][j] + bias[n];
        }
    }
}

// ---------------- K2: scores = QK^T * scale, softmax row-wise -> g_At ----------
__global__ __launch_bounds__(256,1) void k_scores()
{
    __shared__ float sQ[32][68];    // stride 68 floats = 272B: float4-aligned + conflict-free
    __shared__ float sKt[64][68];   // transposed: [d][kcol]
    const int tid = threadIdx.x;
    const int qt = blockIdx.x, h = blockIdx.y, b = blockIdx.z;
    const size_t bh = (size_t)(b*NH+h);
    const float* Q  = g_q + (bh*NT + (size_t)qt*32)*NHD;
    const float* Kp = g_k + bh*NT*NHD;
    float* At = g_At + bh*NT*NT + (size_t)qt*32*NT;

#pragma unroll
    for (int i=0;i<2;i++){
        int f=i*256+tid; int r=f>>4, c4=f&15;
        *(float4*)&sQ[r][c4*4] = *(const float4*)&Q[(size_t)r*NHD + c4*4];
    }
    const int qr = tid>>3, kc = tid&7;   // 32 q-rows x 8 col-groups
    float acc[128];
#pragma unroll
    for (int i=0;i<128;i++) acc[i]=0.f;

#pragma unroll
    for (int kt=0; kt<16; kt++){
        __syncthreads();
#pragma unroll
        for (int i=0;i<4;i++){
            int f=i*256+tid; int c=f>>4, d4=f&15;
            float4 v = *(const float4*)&Kp[(size_t)(kt*64+c)*NHD + d4*4];
            sKt[d4*4+0][c]=v.x; sKt[d4*4+1][c]=v.y;
            sKt[d4*4+2][c]=v.z; sKt[d4*4+3][c]=v.w;
        }
        __syncthreads();
#pragma unroll 8
        for (int d=0; d<64; d++){
            float qv = sQ[qr][d];
            float4 k0 = *(float4*)&sKt[d][kc*8];
            float4 k1 = *(float4*)&sKt[d][kc*8+4];
            acc[kt*8+0] += qv*k0.x;
            acc[kt*8+1] += qv*k0.y;
            acc[kt*8+2] += qv*k0.z;
            acc[kt*8+3] += qv*k0.w;
            acc[kt*8+4] += qv*k1.x;
            acc[kt*8+5] += qv*k1.y;
            acc[kt*8+6] += qv*k1.z;
            acc[kt*8+7] += qv*k1.w;
        }
    }
    // softmax across the 8 lanes sharing qr (each holds 128 of 1024 entries)
    const float scale = 0.125f;
    float mx = -1e30f;
#pragma unroll
    for (int i=0;i<128;i++) mx = fmaxf(mx, acc[i]);
#pragma unroll
    for (int off=1; off<8; off<<=1) mx = fmaxf(mx, __shfl_xor_sync(0xffffffffu, mx, off));
    const float msc = mx*scale;
    float sum = 0.f;
#pragma unroll
    for (int i=0;i<128;i++){
        float p = __expf(fmaf(acc[i], scale, -msc));
        acc[i]=p; sum += p;
    }
#pragma unroll
    for (int off=1; off<8; off<<=1) sum += __shfl_xor_sync(0xffffffffu, sum, off);
    const float inv = 1.0f/sum;
    float* row = At + (size_t)qr*NT;
#pragma unroll
    for (int kt=0;kt<16;kt++){
#pragma unroll
        for (int j4=0;j4<2;j4++){
            float4 v;
            v.x = acc[kt*8+j4*4+0]*inv;
            v.y = acc[kt*8+j4*4+1]*inv;
            v.z = acc[kt*8+j4*4+2]*inv;
            v.w = acc[kt*8+j4*4+3]*inv;
            *(float4*)&row[kt*64 + kc*8 + j4*4] = v;
        }
    }
}

// ------------- K3: R_f + masked-softmax denominators (per head, per row) -------
__global__ __launch_bounds__(256) void k_gate(const float* __restrict__ cw,
                                              const float* __restrict__ cbp)
{
    const int tid=threadIdx.x;
    const int q=blockIdx.x, b=blockIdx.y;
    float w[NH];
#pragma unroll
    for (int h=0;h<NH;h++) w[h]=cw[h];
    const float cb = cbp[0];
    float denf[NH], denr[NH];
#pragma unroll
    for (int h=0;h<NH;h++){ denf[h]=0.f; denr[h]=0.f; }

    const float* Ap = g_At + ((size_t)(b*NH)*NT + q)*NT;   // head h at +h*NT*NT
    float* Rp = g_Rf + ((size_t)b*NT + q)*NT;
#pragma unroll
    for (int kk=0; kk<4; kk++){
        int k = kk*256 + tid;
        float a[NH];
#pragma unroll
        for (int h=0;h<NH;h++) a[h] = Ap[(size_t)h*NT*NT + k];
        float lin = cb;
#pragma unroll
        for (int h=0;h<NH;h++) lin = fmaf(w[h], a[h], lin);
        float r = 1.0f/(1.0f + expf(-lin));   // accurate exp: threshold compare below
        Rp[k] = r;
        bool bf = (r <= 0.5f);
        bool br = ((1.0f - r) <= 0.5f);
#pragma unroll
        for (int h=0;h<NH;h++){
            float e = __expf(a[h]);           // z in [0,1]; exp(z*m): m=0 -> 1
            denf[h] += bf ? e : 1.0f;
            denr[h] += br ? e : 1.0f;
        }
    }
    __shared__ float red[8][16];
    const int lane = tid&31, warp = tid>>5;
#pragma unroll
    for (int v=0; v<16; v++){
        float val = (v<8)? denf[v] : denr[v-8];
#pragma unroll
        for (int off=16; off>0; off>>=1) val += __shfl_down_sync(0xffffffffu, val, off);
        if (lane==0) red[warp][v]=val;
    }
    __syncthreads();
    if (tid < 16){
        float s=0.f;
#pragma unroll
        for (int wp=0; wp<8; wp++) s += red[wp][tid];
        int h = tid & 7;
        float inv = 1.0f/s;
        if (tid < 8) g_invf[((size_t)(b*NH+h))*NT + q] = inv;
        else         g_invr[((size_t)(b*NH+h))*NT + q] = inv;
    }
}

// ------------- K4: T_f / T_r = softmax(A_t*M) @ V, P recomputed on the fly ----
__global__ __launch_bounds__(256) void k_pv()
{
    __shared__ float sV [32][64];
    __shared__ float sPf[64][33];
    __shared__ float sPr[64][33];
    __shared__ float sInvF[64], sInvR[64];
    const int tid=threadIdx.x;
    const int qt=blockIdx.x, h=blockIdx.y, b=blockIdx.z;
    const int q0 = qt*64;
    const size_t bh = (size_t)(b*NH+h);
    const float* At = g_At + bh*NT*NT + (size_t)q0*NT;
    const float* Rf = g_Rf + ((size_t)b*NT + q0)*NT;
    const float* V  = g_v  + bh*NT*NHD;
    if (tid<64){
        sInvF[tid]=g_invf[bh*NT+q0+tid];
        sInvR[tid]=g_invr[bh*NT+q0+tid];
    }
    const int ty=tid>>4, tx=tid&15;
    float af[4][4], ar[4][4];
#pragma unroll
    for (int i=0;i<4;i++)
#pragma unroll
        for (int j=0;j<4;j++){ af[i][j]=0.f; ar[i][j]=0.f; }

    for (int kt=0; kt<32; kt++){
        int k0=kt*32;
        __syncthreads();
#pragma unroll
        for (int i=0;i<8;i++){                 // P tile: 64q x 32k
            int f=i*256+tid; int qq=f>>5, kk=f&31;
            float a = At[(size_t)qq*NT + k0+kk];
            float r = Rf[(size_t)qq*NT + k0+kk];
            float e = __expf(a);
            sPf[qq][kk] = ((r <= 0.5f)        ? e : 1.0f) * sInvF[qq];
            sPr[qq][kk] = (((1.0f-r) <= 0.5f) ? e : 1.0f) * sInvR[qq];
        }
#pragma unroll
        for (int i=0;i<2;i++){                 // V tile: 32k x 64d
            int f=i*256+tid; int kk=f>>4, d4=f&15;
            *(float4*)&sV[kk][d4*4] = *(const float4*)&V[(size_t)(k0+kk)*NHD + d4*4];
        }
        __syncthreads();
#pragma unroll 8
        for (int kk=0; kk<32; kk++){
            float4 v = *(float4*)&sV[kk][tx*4];
#pragma unroll
            for (int i=0;i<4;i++){
                float pf = sPf[ty*4+i][kk];
                float pr = sPr[ty*4+i][kk];
                af[i][0]+=pf*v.x; af[i][1]+=pf*v.y; af[i][2]+=pf*v.z; af[i][3]+=pf*v.w;
                ar[i][0]+=pr*v.x; ar[i][1]+=pr*v.y; ar[i][2]+=pr*v.z; ar[i][3]+=pr*v.w;
            }
        }
    }
#pragma unroll
    for (int i=0;i<4;i++){
        int q = q0 + ty*4 + i;
        size_t o = ((size_t)b*NT + q)*NHDIM + h*NHD + tx*4;
        float4 vf; vf.x=af[i][0]; vf.y=af[i][1]; vf.z=af[i][2]; vf.w=af[i][3];
        float4 vr; vr.x=ar[i][0]; vr.y=ar[i][1]; vr.z=ar[i][2]; vr.w=ar[i][3];
        *(float4*)&g_Tf[o] = vf;
        *(float4*)&g_Tr[o] = vr;
    }
}

// ------------- K5: four output GEMMs fused + softmax gate --------------------
__global__ __launch_bounds__(256) void k_final(const float* __restrict__ Wfh, const float* __restrict__ bfh,
                                               const float* __restrict__ Wfg, const float* __restrict__ bfg,
                                               const float* __restrict__ Wrh, const float* __restrict__ brh,
                                               const float* __restrict__ Wrg, const float* __restrict__ brg,
                                               float* __restrict__ out)
{
    __shared__ float sTf[64][16];
    __shared__ float sTr[64][16];
    __shared__ float sW[4][16][32];
    const int tid=threadIdx.x;
    const int n0=blockIdx.x*32, m0=blockIdx.y*64;
    const int ty=tid>>4, tx=tid&15;     // 4 rows x 2 cols per thread, x4 gemms
    float aFf[4][2], aGf[4][2], aFr[4][2], aGr[4][2];
#pragma unroll
    for (int i=0;i<4;i++)
#pragma unroll
        for (int j=0;j<2;j++){ aFf[i][j]=0.f; aGf[i][j]=0.f; aFr[i][j]=0.f; aGr[i][j]=0.f; }

    for (int ko=0; ko<NHDIM; ko+=16){
        __syncthreads();
        {
            int r=tid>>2, c4=tid&3;
            *(float4*)&sTf[r][c4*4] = *(const float4*)&g_Tf[(size_t)(m0+r)*NHDIM + ko + c4*4];
            *(float4*)&sTr[r][c4*4] = *(const float4*)&g_Tr[(size_t)(m0+r)*NHDIM + ko + c4*4];
        }
#pragma unroll
        for (int i=0;i<2;i++){
            int f=i*256+tid; int mat=f>>7, rem=f&127; int r=rem>>3, c4=rem&7;
            const float* Wp = (mat==0)?Wfh:(mat==1)?Wfg:(mat==2)?Wrh:Wrg;
            *(float4*)&sW[mat][r][c4*4] = *(const float4*)&Wp[(size_t)(ko+r)*NHDIM + n0 + c4*4];
        }
        __syncthreads();
#pragma unroll
        for (int kk=0;kk<16;kk++){
            float tf[4], tr[4];
#pragma unroll
            for (int i=0;i<4;i++){ tf[i]=sTf[ty*4+i][kk]; tr[i]=sTr[ty*4+i][kk]; }
            float2 wfh_=*(float2*)&sW[0][kk][tx*2];
            float2 wfg_=*(float2*)&sW[1][kk][tx*2];
            float2 wrh_=*(float2*)&sW[2][kk][tx*2];
            float2 wrg_=*(float2*)&sW[3][kk][tx*2];
#pragma unroll
            for (int i=0;i<4;i++){
                aFf[i][0]+=tf[i]*wfh_.x; aFf[i][1]+=tf[i]*wfh_.y;
                aGf[i][0]+=tf[i]*wfg_.x; aGf[i][1]+=tf[i]*wfg_.y;
                aFr[i][0]+=tr[i]*wrh_.x; aFr[i][1]+=tr[i]*wrh_.y;
                aGr[i][0]+=tr[i]*wrg_.x; aGr[i][1]+=tr[i]*wrg_.y;
            }
        }
    }
#pragma unroll
    for (int i=0;i<4;i++){
        int m = m0+ty*4+i;
#pragma unroll
        for (int j=0;j<2;j++){
            int n = n0+tx*2+j;
            float Ff = aFf[i][j] + bfh[n];
            float Gf = 1.f/(1.f + __expf(-(aGf[i][j] + bfg[n])));
            float Fr = aFr[i][j] + brh[n];
            float Gr = 1.f/(1.f + __expf(-(aGr[i][j] + brg[n])));
            float wv = 1.f/(1.f + __expf(-(Gf - Gr)));   // softmax over {Gf,Gr}
            out[(size_t)m*NHDIM + n] = Ff*wv + Fr*(1.f - wv);
        }
    }
}

// -------------------------------- launch --------------------------------------
extern "C" void kernel_launch(void* const* d_in, const int* in_sizes, int n_in,
                              void* d_out, int out_size)
{
    const float* x   = (const float*)d_in[0];
    const float* Wq  = (const float*)d_in[1];
    const float* bq  = (const float*)d_in[2];
    const float* Wk  = (const float*)d_in[3];
    const float* bk  = (const float*)d_in[4];
    const float* Wv  = (const float*)d_in[5];
    const float* bv  = (const float*)d_in[6];
    const float* cw  = (const float*)d_in[7];
    const float* cb  = (const float*)d_in[8];
    const float* Wfh = (const float*)d_in[9];
    const float* bfh = (const float*)d_in[10];
    const float* Wfg = (const float*)d_in[11];
    const float* bfg = (const float*)d_in[12];
    const float* Wrh = (const float*)d_in[13];
    const float* brh = (const float*)d_in[14];
    const float* Wrg = (const float*)d_in[15];
    const float* brg = (const float*)d_in[16];
    float* out = (float*)d_out;

    dim3 gProj(8, 64);
    k_proj<0><<<gProj, 256>>>(x, Wq, bq);
    k_proj<1><<<gProj, 256>>>(x, Wk, bk);
    k_proj<2><<<gProj, 256>>>(x, Wv, bv);
    k_scores<<<dim3(32, 8, 4), 256>>>();
    k_gate  <<<dim3(1024, 4), 256>>>(cw, cb);
    k_pv    <<<dim3(16, 8, 4), 256>>>();
    k_final <<<dim3(16, 64), 256>>>(Wfh, bfh, Wfg, bfg, Wrh, brh, Wrg, brg, out);
}

// round 4
// speedup vs baseline: 1.5727x; 1.5727x over previous
#include <cuda_runtime.h>

#define NB 4
#define NT 1024
#define ND 512
#define NH 8
#define NHD 64
#define NHDIM 512   // NH*NHD

// ---------------- scratch (static device arrays; no allocation) ----------------
__device__ float g_q [NB*NH*NT*NHD];                 // [b,h,t,d]   8 MB
__device__ float g_k [NB*NH*NT*NHD];
__device__ float g_v [NB*NH*NT*NHD];
__device__ float g_At[(size_t)NB*NH*NT*NT];          // raw scaled scores -> then E=exp(A_t)
__device__ float g_Rf[(size_t)NB*NT*NT];             // gate pre-activation lin (sign = mask)
__device__ float g_invf[NB*NH*NT];                   // 1/denominator per row
__device__ float g_invr[NB*NH*NT];
__device__ float g_Tf[NB*NT*NHDIM];                  // [b,t, h*64+d]  8 MB
__device__ float g_Tr[NB*NT*NHDIM];

// ---------------- K1: projection GEMM, C = X@W + b, permuted to [b,h,t,d] -----
template<int SEL>
__global__ __launch_bounds__(256) void k_proj(const float* __restrict__ X,
                                              const float* __restrict__ W,
                                              const float* __restrict__ bias)
{
    __shared__ float sA[64][16];
    __shared__ float sB[16][64];
    const int tid = threadIdx.x;
    const int m0 = blockIdx.y*64, n0 = blockIdx.x*64;
    const int ty = tid>>4, tx = tid&15;
    float acc[4][4];
#pragma unroll
    for (int i=0;i<4;i++)
#pragma unroll
        for (int j=0;j<4;j++) acc[i][j]=0.f;

    for (int ko=0; ko<ND; ko+=16){
        {
            int r = tid>>2, c4 = tid&3;
            *(float4*)&sA[r][c4*4] = *(const float4*)&X[(size_t)(m0+r)*ND + ko + c4*4];
        }
        {
            int r = tid>>4, c = tid&15;
            *(float4*)&sB[r][c*4] = *(const float4*)&W[(size_t)(ko+r)*NHDIM + n0 + c*4];
        }
        __syncthreads();
#pragma unroll
        for (int kk=0;kk<16;kk++){
            float a0=sA[ty*4+0][kk], a1=sA[ty*4+1][kk];
            float a2=sA[ty*4+2][kk], a3=sA[ty*4+3][kk];
            float4 bv = *(float4*)&sB[kk][tx*4];
            acc[0][0]+=a0*bv.x; acc[0][1]+=a0*bv.y; acc[0][2]+=a0*bv.z; acc[0][3]+=a0*bv.w;
            acc[1][0]+=a1*bv.x; acc[1][1]+=a1*bv.y; acc[1][2]+=a1*bv.z; acc[1][3]+=a1*bv.w;
            acc[2][0]+=a2*bv.x; acc[2][1]+=a2*bv.y; acc[2][2]+=a2*bv.z; acc[2][3]+=a2*bv.w;
            acc[3][0]+=a3*bv.x; acc[3][1]+=a3*bv.y; acc[3][2]+=a3*bv.z; acc[3][3]+=a3*bv.w;
        }
        __syncthreads();
    }
    float* dst = (SEL==0)?g_q:(SEL==1)?g_k:g_v;
#pragma unroll
    for (int i=0;i<4;i++){
        int m = m0+ty*4+i;
        int b = m>>10, t = m&1023;
#pragma unroll
        for (int j=0;j<4;j++){
            int n = n0+tx*4+j;
            int h = n>>6, d = n&63;
            dst[(((size_t)(b*NH+h)*NT)+t)*NHD + d] = acc[i][j] + bias[n];
        }
    }
}

// ---------------- K2: pure GEMM  S = (Q*scale) @ K^T  -> g_At (raw) -----------
// 128x128 tile per block, 256 threads, 8x8 per thread. K=64 split in 2 halves.
__global__ __launch_bounds__(256) void k_scores()
{
    __shared__ float sQt[32][132];   // [d][q], stride 132 (float4-aligned, CF)
    __shared__ float sKt[32][132];   // [d][k]
    const int tid = threadIdx.x;
    const int k0 = blockIdx.x*128, q0 = blockIdx.y*128;
    const size_t bh = blockIdx.z;
    const float* Q  = g_q + (bh*NT + (size_t)q0)*NHD;
    const float* Kp = g_k + (bh*NT + (size_t)k0)*NHD;
    float* S = g_At + bh*NT*NT + (size_t)q0*NT + k0;
    const int ty = tid>>4, tx = tid&15;

    float acc[8][8];
#pragma unroll
    for (int i=0;i<8;i++)
#pragma unroll
        for (int j=0;j<8;j++) acc[i][j]=0.f;

#pragma unroll
    for (int half=0; half<2; half++){
        // load 128 rows x 32 d, transposed into smem
#pragma unroll
        for (int i=0;i<4;i++){
            int f = i*256 + tid;
            int r = f>>3, c4 = f&7;          // r: 0..127, c4: 0..7 (float4 of d)
            float4 a = *(const float4*)&Q [(size_t)r*NHD + half*32 + c4*4];
            float4 b = *(const float4*)&Kp[(size_t)r*NHD + half*32 + c4*4];
            sQt[c4*4+0][r]=a.x*0.125f; sQt[c4*4+1][r]=a.y*0.125f;
            sQt[c4*4+2][r]=a.z*0.125f; sQt[c4*4+3][r]=a.w*0.125f;
            sKt[c4*4+0][r]=b.x; sKt[c4*4+1][r]=b.y;
            sKt[c4*4+2][r]=b.z; sKt[c4*4+3][r]=b.w;
        }
        __syncthreads();
#pragma unroll 8
        for (int d=0; d<32; d++){
            float4 a0 = *(float4*)&sQt[d][ty*8];
            float4 a1 = *(float4*)&sQt[d][ty*8+4];
            float4 b0 = *(float4*)&sKt[d][tx*8];
            float4 b1 = *(float4*)&sKt[d][tx*8+4];
            float av[8] = {a0.x,a0.y,a0.z,a0.w,a1.x,a1.y,a1.z,a1.w};
            float bv[8] = {b0.x,b0.y,b0.z,b0.w,b1.x,b1.y,b1.z,b1.w};
#pragma unroll
            for (int i=0;i<8;i++)
#pragma unroll
                for (int j=0;j<8;j++) acc[i][j] = fmaf(av[i], bv[j], acc[i][j]);
        }
        __syncthreads();
    }
#pragma unroll
    for (int i=0;i<8;i++){
        float* row = S + (size_t)(ty*8+i)*NT + tx*8;
        float4 v0; v0.x=acc[i][0]; v0.y=acc[i][1]; v0.z=acc[i][2]; v0.w=acc[i][3];
        float4 v1; v1.x=acc[i][4]; v1.y=acc[i][5]; v1.z=acc[i][6]; v1.w=acc[i][7];
        *(float4*)&row[0] = v0;
        *(float4*)&row[4] = v1;
    }
}

// ------------- K3: softmax (all heads) + gate + masked denominators -----------
// One block per (b,q). Converts raw S -> E = exp(softmax(S)) IN PLACE in g_At,
// writes gate pre-activation lin to g_Rf, and 1/den to g_invf/g_invr.
__global__ __launch_bounds__(256) void k_gate(const float* __restrict__ cw,
                                              const float* __restrict__ cbp)
{
    __shared__ float sS[8][1024];     // 32KB: row of all 8 heads
    __shared__ float sInv[8];
    __shared__ float red[8][16];
    const int tid = threadIdx.x;
    const int q = blockIdx.x, b = blockIdx.y;
    const size_t base = ((size_t)(b*NH))*NT*NT + (size_t)q*NT;   // + h*NT*NT

    // load all 8 head-rows (coalesced float4)
#pragma unroll
    for (int i=0;i<8;i++){
        int f = i*256 + tid;          // 0..2047
        int h = f>>8, c4 = f&255;
        *(float4*)&sS[h][c4*4] = *(const float4*)&g_At[base + (size_t)h*NT*NT + c4*4];
    }
    __syncthreads();

    // per-warp softmax stats: warp w owns head w
    const int warp = tid>>5, lane = tid&31;
    {
        float m = -1e30f;
#pragma unroll
        for (int j=0;j<32;j++) m = fmaxf(m, sS[warp][lane + 32*j]);
#pragma unroll
        for (int off=16; off>0; off>>=1) m = fmaxf(m, __shfl_xor_sync(0xffffffffu, m, off));
        float sum = 0.f;
#pragma unroll
        for (int j=0;j<32;j++){
            float e = __expf(sS[warp][lane + 32*j] - m);
            sS[warp][lane + 32*j] = e;     // unnormalized
            sum += e;
        }
#pragma unroll
        for (int off=16; off>0; off>>=1) sum += __shfl_xor_sync(0xffffffffu, sum, off);
        if (lane==0) sInv[warp] = 1.0f/sum;
    }
    __syncthreads();

    float w[NH];
#pragma unroll
    for (int h=0;h<NH;h++) w[h]=cw[h];
    const float cb = cbp[0];
    float inv[NH];
#pragma unroll
    for (int h=0;h<NH;h++) inv[h]=sInv[h];

    float denf[NH], denr[NH];
#pragma unroll
    for (int h=0;h<NH;h++){ denf[h]=0.f; denr[h]=0.f; }
    float* lin_out = g_Rf + ((size_t)b*NT + q)*NT;

#pragma unroll
    for (int kk=0; kk<4; kk++){
        int k = kk*256 + tid;
        float A[NH];
        float lin = cb;
#pragma unroll
        for (int h=0;h<NH;h++){ A[h] = sS[h][k]*inv[h]; lin = fmaf(w[h], A[h], lin); }
        lin_out[k] = lin;
        bool bf = (lin <= 0.f);       // r = sigmoid(lin) <= 0.5
        bool br = (lin >= 0.f);       // 1-r <= 0.5
#pragma unroll
        for (int h=0;h<NH;h++){
            float E = __expf(A[h]);
            g_At[base + (size_t)h*NT*NT + k] = E;     // in-place: this block owns the row
            denf[h] += bf ? E : 1.0f;
            denr[h] += br ? E : 1.0f;
        }
    }
    // block reduction of 16 values
#pragma unroll
    for (int v=0; v<16; v++){
        float val = (v<8)? denf[v] : denr[v-8];
#pragma unroll
        for (int off=16; off>0; off>>=1) val += __shfl_down_sync(0xffffffffu, val, off);
        if (lane==0) red[warp][v]=val;
    }
    __syncthreads();
    if (tid < 16){
        float s=0.f;
#pragma unroll
        for (int wp=0; wp<8; wp++) s += red[wp][tid];
        int h = tid & 7;
        float is = 1.0f/s;
        if (tid < 8) g_invf[((size_t)(b*NH+h))*NT + q] = is;
        else         g_invr[((size_t)(b*NH+h))*NT + q] = is;
    }
}

// ------------- K4: T_f / T_r = P @ V, P from stored E (no exp here) ----------
__global__ __launch_bounds__(256) void k_pv()
{
    __shared__ float sPf[32][65];   // [k][q], odd stride: CF scalar access
    __shared__ float sPr[32][65];
    __shared__ float sV [32][68];   // [k][d], float4 loads
    __shared__ float sInvF[64], sInvR[64];
    const int tid=threadIdx.x;
    const int qt=blockIdx.x, h=blockIdx.y, b=blockIdx.z;
    const int q0 = qt*64;
    const size_t bh = (size_t)(b*NH+h);
    const float* E = g_At + bh*NT*NT + (size_t)q0*NT;
    const float* L = g_Rf + ((size_t)b*NT + q0)*NT;
    const float* V = g_v  + bh*NT*NHD;
    if (tid<64){
        sInvF[tid]=g_invf[bh*NT+q0+tid];
        sInvR[tid]=g_invr[bh*NT+q0+tid];
    }
    const int ty=tid>>4, tx=tid&15;
    float af[4][4], ar[4][4];
#pragma unroll
    for (int i=0;i<4;i++)
#pragma unroll
        for (int j=0;j<4;j++){ af[i][j]=0.f; ar[i][j]=0.f; }

    for (int kt=0; kt<32; kt++){
        int k0=kt*32;
        __syncthreads();
#pragma unroll
        for (int i=0;i<8;i++){                 // P tile transposed: [k][q]
            int f=i*256+tid; int qq=f>>5, kk=f&31;    // coalesced gmem (kk fast)
            float e = E[(size_t)qq*NT + k0+kk];
            float l = L[(size_t)qq*NT + k0+kk];
            sPf[kk][qq] = ((l <= 0.f) ? e : 1.0f) * sInvF[qq];
            sPr[kk][qq] = ((l >= 0.f) ? e : 1.0f) * sInvR[qq];
        }
#pragma unroll
        for (int i=0;i<2;i++){                 // V tile: 32k x 64d
            int f=i*256+tid; int kk=f>>4, d4=f&15;
            *(float4*)&sV[kk][d4*4] = *(const float4*)&V[(size_t)(k0+kk)*NHD + d4*4];
        }
        __syncthreads();
#pragma unroll 8
        for (int kk=0; kk<32; kk++){
            float4 v = *(float4*)&sV[kk][tx*4];
            float pf0=sPf[kk][ty*4+0], pf1=sPf[kk][ty*4+1], pf2=sPf[kk][ty*4+2], pf3=sPf[kk][ty*4+3];
            float pr0=sPr[kk][ty*4+0], pr1=sPr[kk][ty*4+1], pr2=sPr[kk][ty*4+2], pr3=sPr[kk][ty*4+3];
            af[0][0]+=pf0*v.x; af[0][1]+=pf0*v.y; af[0][2]+=pf0*v.z; af[0][3]+=pf0*v.w;
            af[1][0]+=pf1*v.x; af[1][1]+=pf1*v.y; af[1][2]+=pf1*v.z; af[1][3]+=pf1*v.w;
            af[2][0]+=pf2*v.x; af[2][1]+=pf2*v.y; af[2][2]+=pf2*v.z; af[2][3]+=pf2*v.w;
            af[3][0]+=pf3*v.x; af[3][1]+=pf3*v.y; af[3][2]+=pf3*v.z; af[3][3]+=pf3*v.w;
            ar[0][0]+=pr0*v.x; ar[0][1]+=pr0*v.y; ar[0][2]+=pr0*v.z; ar[0][3]+=pr0*v.w;
            ar[1][0]+=pr1*v.x; ar[1][1]+=pr1*v.y; ar[1][2]+=pr1*v.z; ar[1][3]+=pr1*v.w;
            ar[2][0]+=pr2*v.x; ar[2][1]+=pr2*v.y; ar[2][2]+=pr2*v.z; ar[2][3]+=pr2*v.w;
            ar[3][0]+=pr3*v.x; ar[3][1]+=pr3*v.y; ar[3][2]+=pr3*v.z; ar[3][3]+=pr3*v.w;
        }
    }
#pragma unroll
    for (int i=0;i<4;i++){
        int q = q0 + ty*4 + i;
        size_t o = ((size_t)b*NT + q)*NHDIM + h*NHD + tx*4;
        float4 vf; vf.x=af[i][0]; vf.y=af[i][1]; vf.z=af[i][2]; vf.w=af[i][3];
        float4 vr; vr.x=ar[i][0]; vr.y=ar[i][1]; vr.z=ar[i][2]; vr.w=ar[i][3];
        *(float4*)&g_Tf[o] = vf;
        *(float4*)&g_Tr[o] = vr;
    }
}

// ------------- K5: four output GEMMs fused + softmax gate --------------------
__global__ __launch_bounds__(256) void k_final(const float* __restrict__ Wfh, const float* __restrict__ bfh,
                                               const float* __restrict__ Wfg, const float* __restrict__ bfg,
                                               const float* __restrict__ Wrh, const float* __restrict__ brh,
                                               const float* __restrict__ Wrg, const float* __restrict__ brg,
                                               float* __restrict__ out)
{
    __shared__ float sTf[64][16];
    __shared__ float sTr[64][16];
    __shared__ float sW[4][16][32];
    const int tid=threadIdx.x;
    const int n0=blockIdx.x*32, m0=blockIdx.y*64;
    const int ty=tid>>4, tx=tid&15;     // 4 rows x 2 cols per thread, x4 gemms
    float aFf[4][2], aGf[4][2], aFr[4][2], aGr[4][2];
#pragma unroll
    for (int i=0;i<4;i++)
#pragma unroll
        for (int j=0;j<2;j++){ aFf[i][j]=0.f; aGf[i][j]=0.f; aFr[i][j]=0.f; aGr[i][j]=0.f; }

    for (int ko=0; ko<NHDIM; ko+=16){
        __syncthreads();
        {
            int r=tid>>2, c4=tid&3;
            *(float4*)&sTf[r][c4*4] = *(const float4*)&g_Tf[(size_t)(m0+r)*NHDIM + ko + c4*4];
            *(float4*)&sTr[r][c4*4] = *(const float4*)&g_Tr[(size_t)(m0+r)*NHDIM + ko + c4*4];
        }
#pragma unroll
        for (int i=0;i<2;i++){
            int f=i*256+tid; int mat=f>>7, rem=f&127; int r=rem>>3, c4=rem&7;
            const float* Wp = (mat==0)?Wfh:(mat==1)?Wfg:(mat==2)?Wrh:Wrg;
            *(float4*)&sW[mat][r][c4*4] = *(const float4*)&Wp[(size_t)(ko+r)*NHDIM + n0 + c4*4];
        }
        __syncthreads();
#pragma unroll
        for (int kk=0;kk<16;kk++){
            float tf[4], tr[4];
#pragma unroll
            for (int i=0;i<4;i++){ tf[i]=sTf[ty*4+i][kk]; tr[i]=sTr[ty*4+i][kk]; }
            float2 wfh_=*(float2*)&sW[0][kk][tx*2];
            float2 wfg_=*(float2*)&sW[1][kk][tx*2];
            float2 wrh_=*(float2*)&sW[2][kk][tx*2];
            float2 wrg_=*(float2*)&sW[3][kk][tx*2];
#pragma unroll
            for (int i=0;i<4;i++){
                aFf[i][0]+=tf[i]*wfh_.x; aFf[i][1]+=tf[i]*wfh_.y;
                aGf[i][0]+=tf[i]*wfg_.x; aGf[i][1]+=tf[i]*wfg_.y;
                aFr[i][0]+=tr[i]*wrh_.x; aFr[i][1]+=tr[i]*wrh_.y;
                aGr[i][0]+=tr[i]*wrg_.x; aGr[i][1]+=tr[i]*wrg_.y;
            }
        }
    }
#pragma unroll
    for (int i=0;i<4;i++){
        int m = m0+ty*4+i;
#pragma unroll
        for (int j=0;j<2;j++){
            int n = n0+tx*2+j;
            float Ff = aFf[i][j] + bfh[n];
            float Gf = 1.f/(1.f + __expf(-(aGf[i][j] + bfg[n])));
            float Fr = aFr[i][j] + brh[n];
            float Gr = 1.f/(1.f + __expf(-(aGr[i][j] + brg[n])));
            float wv = 1.f/(1.f + __expf(-(Gf - Gr)));   // softmax over {Gf,Gr}
            out[(size_t)m*NHDIM + n] = Ff*wv + Fr*(1.f - wv);
        }
    }
}

// -------------------------------- launch --------------------------------------
extern "C" void kernel_launch(void* const* d_in, const int* in_sizes, int n_in,
                              void* d_out, int out_size)
{
    const float* x   = (const float*)d_in[0];
    const float* Wq  = (const float*)d_in[1];
    const float* bq  = (const float*)d_in[2];
    const float* Wk  = (const float*)d_in[3];
    const float* bk  = (const float*)d_in[4];
    const float* Wv  = (const float*)d_in[5];
    const float* bv  = (const float*)d_in[6];
    const float* cw  = (const float*)d_in[7];
    const float* cb  = (const float*)d_in[8];
    const float* Wfh = (const float*)d_in[9];
    const float* bfh = (const float*)d_in[10];
    const float* Wfg = (const float*)d_in[11];
    const float* bfg = (const float*)d_in[12];
    const float* Wrh = (const float*)d_in[13];
    const float* brh = (const float*)d_in[14];
    const float* Wrg = (const float*)d_in[15];
    const float* brg = (const float*)d_in[16];
    float* out = (float*)d_out;

    dim3 gProj(8, 64);
    k_proj<0><<<gProj, 256>>>(x, Wq, bq);
    k_proj<1><<<gProj, 256>>>(x, Wk, bk);
    k_proj<2><<<gProj, 256>>>(x, Wv, bv);
    k_scores<<<dim3(8, 8, 32), 256>>>();
    k_gate  <<<dim3(1024, 4), 256>>>(cw, cb);
    k_pv    <<<dim3(16, 8, 4), 256>>>();
    k_final <<<dim3(16, 64), 256>>>(Wfh, bfh, Wfg, bfg, Wrh, brh, Wrg, brg, out);
}

// round 5
// speedup vs baseline: 1.8815x; 1.1963x over previous
#include <cuda_runtime.h>

#define NB 4
#define NT 1024
#define ND 512
#define NH 8
#define NHD 64
#define NHDIM 512   // NH*NHD
#define NM 4096     // NB*NT

// ---------------- scratch (static device arrays; no allocation) ----------------
__device__ float g_q [NB*NH*NT*NHD];                 // [b,h,t,d]   8 MB
__device__ float g_k [NB*NH*NT*NHD];
__device__ float g_v [NB*NH*NT*NHD];
__device__ float g_At[(size_t)NB*NH*NT*NT];          // raw scores -> E=exp(softmax)
__device__ float g_Rf[(size_t)NB*NT*NT];             // gate pre-activation lin (sign = mask)
__device__ float g_invf[NB*NH*NT];
__device__ float g_invr[NB*NH*NT];
__device__ float g_Tf[NM*NHDIM];                     // [b*t, h*64+d]  8 MB
__device__ float g_Tr[NM*NHDIM];
__device__ float g_FG[4*(size_t)NM*NHDIM];           // Ff|Gf|Fr|Gr pre-act, 32 MB

// ---------------- K1: fused QKV projection GEMM, 128x128 tiles ----------------
// C[m, n] over n in [0,1536): mat = n>>9. Epilogue permutes to [b,h,t,d].
__global__ __launch_bounds__(256) void k_proj(const float* __restrict__ X,
                                              const float* __restrict__ Wq,
                                              const float* __restrict__ bq,
                                              const float* __restrict__ Wk,
                                              const float* __restrict__ bk,
                                              const float* __restrict__ Wv,
                                              const float* __restrict__ bv)
{
    __shared__ float sAt[32][132];   // X transposed: [k][m]
    __shared__ float sB [32][132];   // W natural:    [k][n]
    const int tid = threadIdx.x;
    const int n0 = blockIdx.x*128, m0 = blockIdx.y*128;
    const int mat = n0>>9, col0 = n0&511;
    const float* W    = (mat==0)?Wq:(mat==1)?Wk:Wv;
    const float* bias = (mat==0)?bq:(mat==1)?bk:bv;
    float* dst        = (mat==0)?g_q:(mat==1)?g_k:g_v;
    const int ty = tid>>4, tx = tid&15;

    float acc[8][8];
#pragma unroll
    for (int i=0;i<8;i++)
#pragma unroll
        for (int j=0;j<8;j++) acc[i][j]=0.f;

    for (int ko=0; ko<ND; ko+=32){
#pragma unroll
        for (int i=0;i<4;i++){
            int f = i*256 + tid;
            int r = f>>3, c4 = f&7;          // A: row r (m), float4 of k
            float4 a = *(const float4*)&X[(size_t)(m0+r)*ND + ko + c4*4];
            sAt[c4*4+0][r]=a.x; sAt[c4*4+1][r]=a.y;
            sAt[c4*4+2][r]=a.z; sAt[c4*4+3][r]=a.w;
            int kr = f>>5, n4 = f&31;        // B: k-row, float4 of n
            *(float4*)&sB[kr][n4*4] = *(const float4*)&W[(size_t)(ko+kr)*NHDIM + col0 + n4*4];
        }
        __syncthreads();
#pragma unroll 8
        for (int d=0; d<32; d++){
            float4 a0 = *(float4*)&sAt[d][ty*8];
            float4 a1 = *(float4*)&sAt[d][ty*8+4];
            float4 b0 = *(float4*)&sB [d][tx*8];
            float4 b1 = *(float4*)&sB [d][tx*8+4];
            float av[8] = {a0.x,a0.y,a0.z,a0.w,a1.x,a1.y,a1.z,a1.w};
            float bv_[8] = {b0.x,b0.y,b0.z,b0.w,b1.x,b1.y,b1.z,b1.w};
#pragma unroll
            for (int i=0;i<8;i++)
#pragma unroll
                for (int j=0;j<8;j++) acc[i][j] = fmaf(av[i], bv_[j], acc[i][j]);
        }
        __syncthreads();
    }
    float bb[8];
#pragma unroll
    for (int j=0;j<8;j++) bb[j] = bias[col0 + tx*8 + j];
#pragma unroll
    for (int i=0;i<8;i++){
        int m = m0+ty*8+i;
        int b = m>>10, t = m&1023;
        int col = col0 + tx*8;
        int h = col>>6, d = col&63;
        float* p = dst + (((size_t)(b*NH+h)*NT)+t)*NHD + d;
        float4 v0; v0.x=acc[i][0]+bb[0]; v0.y=acc[i][1]+bb[1]; v0.z=acc[i][2]+bb[2]; v0.w=acc[i][3]+bb[3];
        float4 v1; v1.x=acc[i][4]+bb[4]; v1.y=acc[i][5]+bb[5]; v1.z=acc[i][6]+bb[6]; v1.w=acc[i][7]+bb[7];
        *(float4*)&p[0] = v0;
        *(float4*)&p[4] = v1;
    }
}

// ---------------- K2: pure GEMM  S = (Q*scale) @ K^T  -> g_At (raw) -----------
__global__ __launch_bounds__(256) void k_scores()
{
    __shared__ float sQt[32][132];   // [d][q]
    __shared__ float sKt[32][132];   // [d][k]
    const int tid = threadIdx.x;
    const int k0 = blockIdx.x*128, q0 = blockIdx.y*128;
    const size_t bh = blockIdx.z;
    const float* Q  = g_q + (bh*NT + (size_t)q0)*NHD;
    const float* Kp = g_k + (bh*NT + (size_t)k0)*NHD;
    float* S = g_At + bh*NT*NT + (size_t)q0*NT + k0;
    const int ty = tid>>4, tx = tid&15;

    float acc[8][8];
#pragma unroll
    for (int i=0;i<8;i++)
#pragma unroll
        for (int j=0;j<8;j++) acc[i][j]=0.f;

#pragma unroll
    for (int half=0; half<2; half++){
#pragma unroll
        for (int i=0;i<4;i++){
            int f = i*256 + tid;
            int r = f>>3, c4 = f&7;
            float4 a = *(const float4*)&Q [(size_t)r*NHD + half*32 + c4*4];
            float4 b = *(const float4*)&Kp[(size_t)r*NHD + half*32 + c4*4];
            sQt[c4*4+0][r]=a.x*0.125f; sQt[c4*4+1][r]=a.y*0.125f;
            sQt[c4*4+2][r]=a.z*0.125f; sQt[c4*4+3][r]=a.w*0.125f;
            sKt[c4*4+0][r]=b.x; sKt[c4*4+1][r]=b.y;
            sKt[c4*4+2][r]=b.z; sKt[c4*4+3][r]=b.w;
        }
        __syncthreads();
#pragma unroll 8
        for (int d=0; d<32; d++){
            float4 a0 = *(float4*)&sQt[d][ty*8];
            float4 a1 = *(float4*)&sQt[d][ty*8+4];
            float4 b0 = *(float4*)&sKt[d][tx*8];
            float4 b1 = *(float4*)&sKt[d][tx*8+4];
            float av[8] = {a0.x,a0.y,a0.z,a0.w,a1.x,a1.y,a1.z,a1.w};
            float bv[8] = {b0.x,b0.y,b0.z,b0.w,b1.x,b1.y,b1.z,b1.w};
#pragma unroll
            for (int i=0;i<8;i++)
#pragma unroll
                for (int j=0;j<8;j++) acc[i][j] = fmaf(av[i], bv[j], acc[i][j]);
        }
        __syncthreads();
    }
#pragma unroll
    for (int i=0;i<8;i++){
        float* row = S + (size_t)(ty*8+i)*NT + tx*8;
        float4 v0; v0.x=acc[i][0]; v0.y=acc[i][1]; v0.z=acc[i][2]; v0.w=acc[i][3];
        float4 v1; v1.x=acc[i][4]; v1.y=acc[i][5]; v1.z=acc[i][6]; v1.w=acc[i][7];
        *(float4*)&row[0] = v0;
        *(float4*)&row[4] = v1;
    }
}

// ------------- K3: softmax (all heads) + gate + masked denominators -----------
__global__ __launch_bounds__(256) void k_gate(const float* __restrict__ cw,
                                              const float* __restrict__ cbp)
{
    __shared__ float sS[8][1024];
    __shared__ float sInv[8];
    __shared__ float red[8][16];
    const int tid = threadIdx.x;
    const int q = blockIdx.x, b = blockIdx.y;
    const size_t base = ((size_t)(b*NH))*NT*NT + (size_t)q*NT;

#pragma unroll
    for (int i=0;i<8;i++){
        int f = i*256 + tid;
        int h = f>>8, c4 = f&255;
        *(float4*)&sS[h][c4*4] = *(const float4*)&g_At[base + (size_t)h*NT*NT + c4*4];
    }
    __syncthreads();

    const int warp = tid>>5, lane = tid&31;
    {
        float m = -1e30f;
#pragma unroll
        for (int j=0;j<32;j++) m = fmaxf(m, sS[warp][lane + 32*j]);
#pragma unroll
        for (int off=16; off>0; off>>=1) m = fmaxf(m, __shfl_xor_sync(0xffffffffu, m, off));
        float sum = 0.f;
#pragma unroll
        for (int j=0;j<32;j++){
            float e = __expf(sS[warp][lane + 32*j] - m);
            sS[warp][lane + 32*j] = e;
            sum += e;
        }
#pragma unroll
        for (int off=16; off>0; off>>=1) sum += __shfl_xor_sync(0xffffffffu, sum, off);
        if (lane==0) sInv[warp] = 1.0f/sum;
    }
    __syncthreads();

    float w[NH];
#pragma unroll
    for (int h=0;h<NH;h++) w[h]=cw[h];
    const float cb = cbp[0];
    float inv[NH];
#pragma unroll
    for (int h=0;h<NH;h++) inv[h]=sInv[h];

    float denf[NH], denr[NH];
#pragma unroll
    for (int h=0;h<NH;h++){ denf[h]=0.f; denr[h]=0.f; }
    float* lin_out = g_Rf + ((size_t)b*NT + q)*NT;

#pragma unroll
    for (int kk=0; kk<4; kk++){
        int k = kk*256 + tid;
        float A[NH];
        float lin = cb;
#pragma unroll
        for (int h=0;h<NH;h++){ A[h] = sS[h][k]*inv[h]; lin = fmaf(w[h], A[h], lin); }
        lin_out[k] = lin;
        bool bf = (lin <= 0.f);
        bool br = (lin >= 0.f);
#pragma unroll
        for (int h=0;h<NH;h++){
            float E = __expf(A[h]);
            g_At[base + (size_t)h*NT*NT + k] = E;
            denf[h] += bf ? E : 1.0f;
            denr[h] += br ? E : 1.0f;
        }
    }
#pragma unroll
    for (int v=0; v<16; v++){
        float val = (v<8)? denf[v] : denr[v-8];
#pragma unroll
        for (int off=16; off>0; off>>=1) val += __shfl_down_sync(0xffffffffu, val, off);
        if (lane==0) red[warp][v]=val;
    }
    __syncthreads();
    if (tid < 16){
        float s=0.f;
#pragma unroll
        for (int wp=0; wp<8; wp++) s += red[wp][tid];
        int h = tid & 7;
        float is = 1.0f/s;
        if (tid < 8) g_invf[((size_t)(b*NH+h))*NT + q] = is;
        else         g_invr[((size_t)(b*NH+h))*NT + q] = is;
    }
}

// ------------- K4: T_f/T_r = P @ V, 128q x 64d per block, 2 mats --------------
__global__ __launch_bounds__(256) void k_pv()
{
    __shared__ float sPf[32][132];   // [k][q]
    __shared__ float sPr[32][132];
    __shared__ float sV [32][68];    // [k][d]
    __shared__ float sInvF[128], sInvR[128];
    const int tid=threadIdx.x;
    const int qt=blockIdx.x, h=blockIdx.y, b=blockIdx.z;
    const int q0 = qt*128;
    const size_t bh = (size_t)(b*NH+h);
    const float* E = g_At + bh*NT*NT + (size_t)q0*NT;
    const float* L = g_Rf + ((size_t)b*NT + q0)*NT;
    const float* V = g_v  + bh*NT*NHD;
    if (tid<128){
        sInvF[tid]=g_invf[bh*NT+q0+tid];
        sInvR[tid]=g_invr[bh*NT+q0+tid];
    }
    const int ty=tid>>4, tx=tid&15;   // 8 q-rows x 4 d-cols each
    float af[8][4], ar[8][4];
#pragma unroll
    for (int i=0;i<8;i++)
#pragma unroll
        for (int j=0;j<4;j++){ af[i][j]=0.f; ar[i][j]=0.f; }

    for (int kt=0; kt<32; kt++){
        int k0=kt*32;
        __syncthreads();
#pragma unroll
        for (int i=0;i<4;i++){                 // P tiles transposed: [k][q]
            int f=i*256+tid; int qq=f>>3, k4=f&7;
            float4 e = *(const float4*)&E[(size_t)qq*NT + k0 + k4*4];
            float4 l = *(const float4*)&L[(size_t)qq*NT + k0 + k4*4];
            float invf = sInvF[qq], invr = sInvR[qq];
            sPf[k4*4+0][qq] = ((l.x<=0.f)? e.x : 1.f)*invf;
            sPf[k4*4+1][qq] = ((l.y<=0.f)? e.y : 1.f)*invf;
            sPf[k4*4+2][qq] = ((l.z<=0.f)? e.z : 1.f)*invf;
            sPf[k4*4+3][qq] = ((l.w<=0.f)? e.w : 1.f)*invf;
            sPr[k4*4+0][qq] = ((l.x>=0.f)? e.x : 1.f)*invr;
            sPr[k4*4+1][qq] = ((l.y>=0.f)? e.y : 1.f)*invr;
            sPr[k4*4+2][qq] = ((l.z>=0.f)? e.z : 1.f)*invr;
            sPr[k4*4+3][qq] = ((l.w>=0.f)? e.w : 1.f)*invr;
        }
#pragma unroll
        for (int i=0;i<2;i++){                 // V tile: 32k x 64d
            int f=i*256+tid; int kk=f>>4, d4=f&15;
            *(float4*)&sV[kk][d4*4] = *(const float4*)&V[(size_t)(k0+kk)*NHD + d4*4];
        }
        __syncthreads();
#pragma unroll 4
        for (int kk=0; kk<32; kk++){
            float4 v = *(float4*)&sV[kk][tx*4];
            float pf[8], pr[8];
#pragma unroll
            for (int i=0;i<8;i++){ pf[i]=sPf[kk][ty*8+i]; pr[i]=sPr[kk][ty*8+i]; }
#pragma unroll
            for (int i=0;i<8;i++){
                af[i][0]+=pf[i]*v.x; af[i][1]+=pf[i]*v.y; af[i][2]+=pf[i]*v.z; af[i][3]+=pf[i]*v.w;
                ar[i][0]+=pr[i]*v.x; ar[i][1]+=pr[i]*v.y; ar[i][2]+=pr[i]*v.z; ar[i][3]+=pr[i]*v.w;
            }
        }
    }
#pragma unroll
    for (int i=0;i<8;i++){
        int q = q0 + ty*8 + i;
        size_t o = ((size_t)b*NT + q)*NHDIM + h*NHD + tx*4;
        float4 vf; vf.x=af[i][0]; vf.y=af[i][1]; vf.z=af[i][2]; vf.w=af[i][3];
        float4 vr; vr.x=ar[i][0]; vr.y=ar[i][1]; vr.z=ar[i][2]; vr.w=ar[i][3];
        *(float4*)&g_Tf[o] = vf;
        *(float4*)&g_Tr[o] = vr;
    }
}

// ------------- K5: four output GEMMs (blockIdx.z selects), bias fused ---------
__global__ __launch_bounds__(256) void k_gemm4(const float* __restrict__ Wfh, const float* __restrict__ bfh,
                                               const float* __restrict__ Wfg, const float* __restrict__ bfg,
                                               const float* __restrict__ Wrh, const float* __restrict__ brh,
                                               const float* __restrict__ Wrg, const float* __restrict__ brg)
{
    __shared__ float sAt[32][132];   // T transposed: [k][m]
    __shared__ float sB [32][132];   // W natural:    [k][n]
    const int tid = threadIdx.x;
    const int n0 = blockIdx.x*128, m0 = blockIdx.y*128, mat = blockIdx.z;
    const float* A    = (mat<2)? g_Tf : g_Tr;
    const float* W    = (mat==0)?Wfh:(mat==1)?Wfg:(mat==2)?Wrh:Wrg;
    const float* bias = (mat==0)?bfh:(mat==1)?bfg:(mat==2)?brh:brg;
    float* C = g_FG + (size_t)mat*NM*NHDIM;
    const int ty = tid>>4, tx = tid&15;

    float acc[8][8];
#pragma unroll
    for (int i=0;i<8;i++)
#pragma unroll
        for (int j=0;j<8;j++) acc[i][j]=0.f;

    for (int ko=0; ko<NHDIM; ko+=32){
#pragma unroll
        for (int i=0;i<4;i++){
            int f = i*256 + tid;
            int r = f>>3, c4 = f&7;
            float4 a = *(const float4*)&A[(size_t)(m0+r)*NHDIM + ko + c4*4];
            sAt[c4*4+0][r]=a.x; sAt[c4*4+1][r]=a.y;
            sAt[c4*4+2][r]=a.z; sAt[c4*4+3][r]=a.w;
            int kr = f>>5, n4 = f&31;
            *(float4*)&sB[kr][n4*4] = *(const float4*)&W[(size_t)(ko+kr)*NHDIM + n0 + n4*4];
        }
        __syncthreads();
#pragma unroll 8
        for (int d=0; d<32; d++){
            float4 a0 = *(float4*)&sAt[d][ty*8];
            float4 a1 = *(float4*)&sAt[d][ty*8+4];
            float4 b0 = *(float4*)&sB [d][tx*8];
            float4 b1 = *(float4*)&sB [d][tx*8+4];
            float av[8] = {a0.x,a0.y,a0.z,a0.w,a1.x,a1.y,a1.z,a1.w};
            float bv[8] = {b0.x,b0.y,b0.z,b0.w,b1.x,b1.y,b1.z,b1.w};
#pragma unroll
            for (int i=0;i<8;i++)
#pragma unroll
                for (int j=0;j<8;j++) acc[i][j] = fmaf(av[i], bv[j], acc[i][j]);
        }
        __syncthreads();
    }
    float bb[8];
#pragma unroll
    for (int j=0;j<8;j++) bb[j] = bias[n0 + tx*8 + j];
#pragma unroll
    for (int i=0;i<8;i++){
        float* row = C + (size_t)(m0+ty*8+i)*NHDIM + n0 + tx*8;
        float4 v0; v0.x=acc[i][0]+bb[0]; v0.y=acc[i][1]+bb[1]; v0.z=acc[i][2]+bb[2]; v0.w=acc[i][3]+bb[3];
        float4 v1; v1.x=acc[i][4]+bb[4]; v1.y=acc[i][5]+bb[5]; v1.z=acc[i][6]+bb[6]; v1.w=acc[i][7]+bb[7];
        *(float4*)&row[0] = v0;
        *(float4*)&row[4] = v1;
    }
}

// ------------- K6: elementwise gate fuse -------------------------------------
__global__ __launch_bounds__(256) void k_fuse(float* __restrict__ out)
{
    const size_t idx = ((size_t)blockIdx.x*256 + threadIdx.x)*4;
    const size_t n = (size_t)NM*NHDIM;
    float4 Ff = *(const float4*)&g_FG[0*n + idx];
    float4 Gf = *(const float4*)&g_FG[1*n + idx];
    float4 Fr = *(const float4*)&g_FG[2*n + idx];
    float4 Gr = *(const float4*)&g_FG[3*n + idx];
    float4 o;
    {
        float gf = 1.f/(1.f + __expf(-Gf.x)), gr = 1.f/(1.f + __expf(-Gr.x));
        float wv = 1.f/(1.f + __expf(-(gf - gr)));
        o.x = Ff.x*wv + Fr.x*(1.f - wv);
    }
    {
        float gf = 1.f/(1.f + __expf(-Gf.y)), gr = 1.f/(1.f + __expf(-Gr.y));
        float wv = 1.f/(1.f + __expf(-(gf - gr)));
        o.y = Ff.y*wv + Fr.y*(1.f - wv);
    }
    {
        float gf = 1.f/(1.f + __expf(-Gf.z)), gr = 1.f/(1.f + __expf(-Gr.z));
        float wv = 1.f/(1.f + __expf(-(gf - gr)));
        o.z = Ff.z*wv + Fr.z*(1.f - wv);
    }
    {
        float gf = 1.f/(1.f + __expf(-Gf.w)), gr = 1.f/(1.f + __expf(-Gr.w));
        float wv = 1.f/(1.f + __expf(-(gf - gr)));
        o.w = Ff.w*wv + Fr.w*(1.f - wv);
    }
    *(float4*)&out[idx] = o;
}

// -------------------------------- launch --------------------------------------
extern "C" void kernel_launch(void* const* d_in, const int* in_sizes, int n_in,
                              void* d_out, int out_size)
{
    const float* x   = (const float*)d_in[0];
    const float* Wq  = (const float*)d_in[1];
    const float* bq  = (const float*)d_in[2];
    const float* Wk  = (const float*)d_in[3];
    const float* bk  = (const float*)d_in[4];
    const float* Wv  = (const float*)d_in[5];
    const float* bv  = (const float*)d_in[6];
    const float* cw  = (const float*)d_in[7];
    const float* cb  = (const float*)d_in[8];
    const float* Wfh = (const float*)d_in[9];
    const float* bfh = (const float*)d_in[10];
    const float* Wfg = (const float*)d_in[11];
    const float* bfg = (const float*)d_in[12];
    const float* Wrh = (const float*)d_in[13];
    const float* brh = (const float*)d_in[14];
    const float* Wrg = (const float*)d_in[15];
    const float* brg = (const float*)d_in[16];
    float* out = (float*)d_out;

    k_proj  <<<dim3(12, 32), 256>>>(x, Wq, bq, Wk, bk, Wv, bv);
    k_scores<<<dim3(8, 8, 32), 256>>>();
    k_gate  <<<dim3(1024, 4), 256>>>(cw, cb);
    k_pv    <<<dim3(8, 8, 4), 256>>>();
    k_gemm4 <<<dim3(4, 32, 4), 256>>>(Wfh, bfh, Wfg, bfg, Wrh, brh, Wrg, brg);
    k_fuse  <<<2048, 256>>>(out);
}

// round 9
// speedup vs baseline: 2.6529x; 1.4100x over previous
#include <cuda_runtime.h>
#include <cstdint>

#define NB 4
#define NT 1024
#define ND 512
#define NH 8
#define NHD 64
#define NHDIM 512   // NH*NHD
#define NM 4096     // NB*NT

// ---------------- scratch (static device arrays; no allocation) ----------------
__device__ float g_q [NB*NH*NT*NHD];                 // [b,h,t,d]   8 MB
__device__ float g_k [NB*NH*NT*NHD];
__device__ float g_v [NB*NH*NT*NHD];
__device__ float g_At[(size_t)NB*NH*NT*NT];          // raw scores -> E=exp(softmax)
__device__ float g_Rf[(size_t)NB*NT*NT];             // gate pre-activation lin (sign = mask)
__device__ float g_invf[NB*NH*NT];
__device__ float g_invr[NB*NH*NT];
__device__ float g_Tf[NM*NHDIM];                     // [b*t, h*64+d]  8 MB
__device__ float g_Tr[NM*NHDIM];
__device__ float g_FG[4*(size_t)NM*NHDIM];           // Ff|Gf|Fr|Gr pre-act, 32 MB

// ======================= mma.sync tf32 helpers ================================
__device__ __forceinline__ uint32_t f2tf(float f){
    uint32_t r; asm("cvt.rna.tf32.f32 %0, %1;" : "=r"(r) : "f"(f)); return r;
}
__device__ __forceinline__ void mma_tf32(float* c, const uint32_t* a, const uint32_t* b){
    asm volatile("mma.sync.aligned.m16n8k8.row.col.f32.tf32.tf32.f32 "
        "{%0,%1,%2,%3}, {%4,%5,%6,%7}, {%8,%9}, {%0,%1,%2,%3};"
        : "+f"(c[0]), "+f"(c[1]), "+f"(c[2]), "+f"(c[3])
        : "r"(a[0]), "r"(a[1]), "r"(a[2]), "r"(a[3]), "r"(b[0]), "r"(b[1]));
}

#define PA 36    // sA row pad (floats): frag bank = lane -> conflict-free
#define PB 136   // sB row pad (floats): frag bank = 8t+g -> conflict-free

// Mainloop: acc[mi][ni][4] += A[m0+.., k] * W[k, n0+..]^T, K=512, both stride 512.
// 256 threads; CTA tile 128x128; warp (wm,wn) tile 64x32.
__device__ __forceinline__ void mma_mainloop(const float* __restrict__ A, int m0,
                                             const float* __restrict__ W, int n0,
                                             float (*sA)[PA], float (*sB)[PB],
                                             float acc[4][4][4],
                                             int tid, int g, int t, int wm, int wn)
{
    for (int c=0; c<16; c++){
#pragma unroll
        for (int i=0;i<4;i++){
            int f = i*256 + tid;
            int r = f>>3, c4 = f&7;
            float4 v = *(const float4*)&A[(size_t)(m0+r)*512 + c*32 + c4*4];
            uint32_t* pa = (uint32_t*)&sA[r][c4*4];
            pa[0]=f2tf(v.x); pa[1]=f2tf(v.y); pa[2]=f2tf(v.z); pa[3]=f2tf(v.w);
        }
#pragma unroll
        for (int i=0;i<4;i++){
            int f = i*256 + tid;
            int kl = f>>5, n4 = f&31;
            float4 v = *(const float4*)&W[(size_t)(c*32+kl)*512 + n0 + n4*4];
            uint32_t* pb = (uint32_t*)&sB[kl][n4*4];
            pb[0]=f2tf(v.x); pb[1]=f2tf(v.y); pb[2]=f2tf(v.z); pb[3]=f2tf(v.w);
        }
        __syncthreads();
#pragma unroll
        for (int kk=0; kk<4; kk++){
            const int k8 = kk*8;
            uint32_t afr[4][4];
#pragma unroll
            for (int mi=0; mi<4; mi++){
                int rb = wm*64 + mi*16;
                afr[mi][0] = __float_as_uint(sA[rb+g  ][k8+t  ]);
                afr[mi][1] = __float_as_uint(sA[rb+g+8][k8+t  ]);
                afr[mi][2] = __float_as_uint(sA[rb+g  ][k8+t+4]);
                afr[mi][3] = __float_as_uint(sA[rb+g+8][k8+t+4]);
            }
            uint32_t bfr[4][2];
#pragma unroll
            for (int ni=0; ni<4; ni++){
                int nb = wn*32 + ni*8 + g;
                bfr[ni][0] = __float_as_uint(sB[k8+t  ][nb]);
                bfr[ni][1] = __float_as_uint(sB[k8+t+4][nb]);
            }
#pragma unroll
            for (int mi=0; mi<4; mi++)
#pragma unroll
                for (int ni=0; ni<4; ni++)
                    mma_tf32(acc[mi][ni], afr[mi], bfr[ni]);
        }
        __syncthreads();
    }
}

// ---------------- K1: QKV projection, tf32 mma --------------------------------
__global__ __launch_bounds__(256) void k_proj_mma(const float* __restrict__ X,
                                                  const float* __restrict__ Wq,
                                                  const float* __restrict__ bq,
                                                  const float* __restrict__ Wk,
                                                  const float* __restrict__ bk,
                                                  const float* __restrict__ Wv,
                                                  const float* __restrict__ bv)
{
    __shared__ float sA[128][PA];
    __shared__ float sB[32][PB];
    const int tid = threadIdx.x, lane = tid&31, warp = tid>>5;
    const int g = lane>>2, t = lane&3;
    const int wm = warp>>2, wn = warp&3;
    const int n0 = blockIdx.x*128, m0 = blockIdx.y*128;
    const int mat = n0>>9, col0 = n0&511;
    const float* W    = (mat==0)?Wq:(mat==1)?Wk:Wv;
    const float* bias = (mat==0)?bq:(mat==1)?bk:bv;
    float* dst        = (mat==0)?g_q:(mat==1)?g_k:g_v;

    float acc[4][4][4];
#pragma unroll
    for (int mi=0;mi<4;mi++)
#pragma unroll
        for (int ni=0;ni<4;ni++)
#pragma unroll
            for (int r=0;r<4;r++) acc[mi][ni][r]=0.f;

    mma_mainloop(X, m0, W, col0, sA, sB, acc, tid, g, t, wm, wn);

#pragma unroll
    for (int mi=0;mi<4;mi++){
#pragma unroll
        for (int ni=0;ni<4;ni++){
            int colb = col0 + wn*32 + ni*8 + 2*t;
            int h = colb>>6, d = colb&63;
            float b0v = bias[colb], b1v = bias[colb+1];
            int r0 = m0 + wm*64 + mi*16 + g;
#pragma unroll
            for (int half=0; half<2; half++){
                int m = r0 + half*8;
                int b = m>>10, tt = m&1023;
                float2 o;
                o.x = acc[mi][ni][half*2+0] + b0v;
                o.y = acc[mi][ni][half*2+1] + b1v;
                *(float2*)&dst[(((size_t)(b*NH+h))*NT + tt)*NHD + d] = o;
            }
        }
    }
}

// ---------------- K5: four output GEMMs, tf32 mma -----------------------------
__global__ __launch_bounds__(256) void k_gemm4_mma(const float* __restrict__ Wfh, const float* __restrict__ bfh,
                                                   const float* __restrict__ Wfg, const float* __restrict__ bfg,
                                                   const float* __restrict__ Wrh, const float* __restrict__ brh,
                                                   const float* __restrict__ Wrg, const float* __restrict__ brg)
{
    __shared__ float sA[128][PA];
    __shared__ float sB[32][PB];
    const int tid = threadIdx.x, lane = tid&31, warp = tid>>5;
    const int g = lane>>2, t = lane&3;
    const int wm = warp>>2, wn = warp&3;
    const int n0 = blockIdx.x*128, m0 = blockIdx.y*128, mat = blockIdx.z;
    const float* A    = (mat<2)? g_Tf : g_Tr;
    const float* W    = (mat==0)?Wfh:(mat==1)?Wfg:(mat==2)?Wrh:Wrg;
    const float* bias = (mat==0)?bfh:(mat==1)?bfg:(mat==2)?brh:brg;
    float* C = g_FG + (size_t)mat*NM*NHDIM;

    float acc[4][4][4];
#pragma unroll
    for (int mi=0;mi<4;mi++)
#pragma unroll
        for (int ni=0;ni<4;ni++)
#pragma unroll
            for (int r=0;r<4;r++) acc[mi][ni][r]=0.f;

    mma_mainloop(A, m0, W, n0, sA, sB, acc, tid, g, t, wm, wn);

#pragma unroll
    for (int mi=0;mi<4;mi++){
#pragma unroll
        for (int ni=0;ni<4;ni++){
            int colb = n0 + wn*32 + ni*8 + 2*t;
            float b0v = bias[colb], b1v = bias[colb+1];
            int r0 = m0 + wm*64 + mi*16 + g;
#pragma unroll
            for (int half=0; half<2; half++){
                int m = r0 + half*8;
                float2 o;
                o.x = acc[mi][ni][half*2+0] + b0v;
                o.y = acc[mi][ni][half*2+1] + b1v;
                *(float2*)&C[(size_t)m*NHDIM + colb] = o;
            }
        }
    }
}

// ---------------- K2: pure GEMM  S = (Q*scale) @ K^T  -> g_At (raw) -----------
__global__ __launch_bounds__(256) void k_scores()
{
    __shared__ float sQt[32][132];   // [d][q]
    __shared__ float sKt[32][132];   // [d][k]
    const int tid = threadIdx.x;
    const int k0 = blockIdx.x*128, q0 = blockIdx.y*128;
    const size_t bh = blockIdx.z;
    const float* Q  = g_q + (bh*NT + (size_t)q0)*NHD;
    const float* Kp = g_k + (bh*NT + (size_t)k0)*NHD;
    float* S = g_At + bh*NT*NT + (size_t)q0*NT + k0;
    const int ty = tid>>4, tx = tid&15;

    float acc[8][8];
#pragma unroll
    for (int i=0;i<8;i++)
#pragma unroll
        for (int j=0;j<8;j++) acc[i][j]=0.f;

#pragma unroll
    for (int half=0; half<2; half++){
#pragma unroll
        for (int i=0;i<4;i++){
            int f = i*256 + tid;
            int r = f>>3, c4 = f&7;
            float4 a = *(const float4*)&Q [(size_t)r*NHD + half*32 + c4*4];
            float4 b = *(const float4*)&Kp[(size_t)r*NHD + half*32 + c4*4];
            sQt[c4*4+0][r]=a.x*0.125f; sQt[c4*4+1][r]=a.y*0.125f;
            sQt[c4*4+2][r]=a.z*0.125f; sQt[c4*4+3][r]=a.w*0.125f;
            sKt[c4*4+0][r]=b.x; sKt[c4*4+1][r]=b.y;
            sKt[c4*4+2][r]=b.z; sKt[c4*4+3][r]=b.w;
        }
        __syncthreads();
#pragma unroll 8
        for (int d=0; d<32; d++){
            float4 a0 = *(float4*)&sQt[d][ty*8];
            float4 a1 = *(float4*)&sQt[d][ty*8+4];
            float4 b0 = *(float4*)&sKt[d][tx*8];
            float4 b1 = *(float4*)&sKt[d][tx*8+4];
            float av[8] = {a0.x,a0.y,a0.z,a0.w,a1.x,a1.y,a1.z,a1.w};
            float bv[8] = {b0.x,b0.y,b0.z,b0.w,b1.x,b1.y,b1.z,b1.w};
#pragma unroll
            for (int i=0;i<8;i++)
#pragma unroll
                for (int j=0;j<8;j++) acc[i][j] = fmaf(av[i], bv[j], acc[i][j]);
        }
        __syncthreads();
    }
#pragma unroll
    for (int i=0;i<8;i++){
        float* row = S + (size_t)(ty*8+i)*NT + tx*8;
        float4 v0; v0.x=acc[i][0]; v0.y=acc[i][1]; v0.z=acc[i][2]; v0.w=acc[i][3];
        float4 v1; v1.x=acc[i][4]; v1.y=acc[i][5]; v1.z=acc[i][6]; v1.w=acc[i][7];
        *(float4*)&row[0] = v0;
        *(float4*)&row[4] = v1;
    }
}

// ------------- K3: softmax (all heads) + gate + masked denominators -----------
__global__ __launch_bounds__(256) void k_gate(const float* __restrict__ cw,
                                              const float* __restrict__ cbp)
{
    __shared__ float sS[8][1024];
    __shared__ float sInv[8];
    __shared__ float red[8][16];
    const int tid = threadIdx.x;
    const int q = blockIdx.x, b = blockIdx.y;
    const size_t base = ((size_t)(b*NH))*NT*NT + (size_t)q*NT;

#pragma unroll
    for (int i=0;i<8;i++){
        int f = i*256 + tid;
        int h = f>>8, c4 = f&255;
        *(float4*)&sS[h][c4*4] = *(const float4*)&g_At[base + (size_t)h*NT*NT + c4*4];
    }
    __syncthreads();

    const int warp = tid>>5, lane = tid&31;
    {
        float m = -1e30f;
#pragma unroll
        for (int j=0;j<32;j++) m = fmaxf(m, sS[warp][lane + 32*j]);
#pragma unroll
        for (int off=16; off>0; off>>=1) m = fmaxf(m, __shfl_xor_sync(0xffffffffu, m, off));
        float sum = 0.f;
#pragma unroll
        for (int j=0;j<32;j++){
            float e = __expf(sS[warp][lane + 32*j] - m);
            sS[warp][lane + 32*j] = e;
            sum += e;
        }
#pragma unroll
        for (int off=16; off>0; off>>=1) sum += __shfl_xor_sync(0xffffffffu, sum, off);
        if (lane==0) sInv[warp] = 1.0f/sum;
    }
    __syncthreads();

    float w[NH];
#pragma unroll
    for (int h=0;h<NH;h++) w[h]=cw[h];
    const float cb = cbp[0];
    float inv[NH];
#pragma unroll
    for (int h=0;h<NH;h++) inv[h]=sInv[h];

    float denf[NH], denr[NH];
#pragma unroll
    for (int h=0;h<NH;h++){ denf[h]=0.f; denr[h]=0.f; }
    float* lin_out = g_Rf + ((size_t)b*NT + q)*NT;

#pragma unroll
    for (int kk=0; kk<4; kk++){
        int k = kk*256 + tid;
        float A[NH];
        float lin = cb;
#pragma unroll
        for (int h=0;h<NH;h++){ A[h] = sS[h][k]*inv[h]; lin = fmaf(w[h], A[h], lin); }
        lin_out[k] = lin;
        bool bf = (lin <= 0.f);
        bool br = (lin >= 0.f);
#pragma unroll
        for (int h=0;h<NH;h++){
            float E = __expf(A[h]);
            g_At[base + (size_t)h*NT*NT + k] = E;
            denf[h] += bf ? E : 1.0f;
            denr[h] += br ? E : 1.0f;
        }
    }
#pragma unroll
    for (int v=0; v<16; v++){
        float val = (v<8)? denf[v] : denr[v-8];
#pragma unroll
        for (int off=16; off>0; off>>=1) val += __shfl_down_sync(0xffffffffu, val, off);
        if (lane==0) red[warp][v]=val;
    }
    __syncthreads();
    if (tid < 16){
        float s=0.f;
#pragma unroll
        for (int wp=0; wp<8; wp++) s += red[wp][tid];
        int h = tid & 7;
        float is = 1.0f/s;
        if (tid < 8) g_invf[((size_t)(b*NH+h))*NT + q] = is;
        else         g_invr[((size_t)(b*NH+h))*NT + q] = is;
    }
}

// ------------- K4: T_f/T_r = P @ V, 128q x 64d per block, 2 mats --------------
__global__ __launch_bounds__(256) void k_pv()
{
    __shared__ float sPf[32][132];   // [k][q]
    __shared__ float sPr[32][132];
    __shared__ float sV [32][68];    // [k][d]
    __shared__ float sInvF[128], sInvR[128];
    const int tid=threadIdx.x;
    const int qt=blockIdx.x, h=blockIdx.y, b=blockIdx.z;
    const int q0 = qt*128;
    const size_t bh = (size_t)(b*NH+h);
    const float* E = g_At + bh*NT*NT + (size_t)q0*NT;
    const float* L = g_Rf + ((size_t)b*NT + q0)*NT;
    const float* V = g_v  + bh*NT*NHD;
    if (tid<128){
        sInvF[tid]=g_invf[bh*NT+q0+tid];
        sInvR[tid]=g_invr[bh*NT+q0+tid];
    }
    const int ty=tid>>4, tx=tid&15;   // 8 q-rows x 4 d-cols each
    float af[8][4], ar[8][4];
#pragma unroll
    for (int i=0;i<8;i++)
#pragma unroll
        for (int j=0;j<4;j++){ af[i][j]=0.f; ar[i][j]=0.f; }

    for (int kt=0; kt<32; kt++){
        int k0=kt*32;
        __syncthreads();
#pragma unroll
        for (int i=0;i<4;i++){                 // P tiles transposed: [k][q]
            int f=i*256+tid; int qq=f>>3, k4=f&7;
            float4 e = *(const float4*)&E[(size_t)qq*NT + k0 + k4*4];
            float4 l = *(const float4*)&L[(size_t)qq*NT + k0 + k4*4];
            float invf = sInvF[qq], invr = sInvR[qq];
            sPf[k4*4+0][qq] = ((l.x<=0.f)? e.x : 1.f)*invf;
            sPf[k4*4+1][qq] = ((l.y<=0.f)? e.y : 1.f)*invf;
            sPf[k4*4+2][qq] = ((l.z<=0.f)? e.z : 1.f)*invf;
            sPf[k4*4+3][qq] = ((l.w<=0.f)? e.w : 1.f)*invf;
            sPr[k4*4+0][qq] = ((l.x>=0.f)? e.x : 1.f)*invr;
            sPr[k4*4+1][qq] = ((l.y>=0.f)? e.y : 1.f)*invr;
            sPr[k4*4+2][qq] = ((l.z>=0.f)? e.z : 1.f)*invr;
            sPr[k4*4+3][qq] = ((l.w>=0.f)? e.w : 1.f)*invr;
        }
#pragma unroll
        for (int i=0;i<2;i++){                 // V tile: 32k x 64d
            int f=i*256+tid; int kk=f>>4, d4=f&15;
            *(float4*)&sV[kk][d4*4] = *(const float4*)&V[(size_t)(k0+kk)*NHD + d4*4];
        }
        __syncthreads();
#pragma unroll 4
        for (int kk=0; kk<32; kk++){
            float4 v = *(float4*)&sV[kk][tx*4];
            float pf[8], pr[8];
#pragma unroll
            for (int i=0;i<8;i++){ pf[i]=sPf[kk][ty*8+i]; pr[i]=sPr[kk][ty*8+i]; }
#pragma unroll
            for (int i=0;i<8;i++){
                af[i][0]+=pf[i]*v.x; af[i][1]+=pf[i]*v.y; af[i][2]+=pf[i]*v.z; af[i][3]+=pf[i]*v.w;
                ar[i][0]+=pr[i]*v.x; ar[i][1]+=pr[i]*v.y; ar[i][2]+=pr[i]*v.z; ar[i][3]+=pr[i]*v.w;
            }
        }
    }
#pragma unroll
    for (int i=0;i<8;i++){
        int q = q0 + ty*8 + i;
        size_t o = ((size_t)b*NT + q)*NHDIM + h*NHD + tx*4;
        float4 vf; vf.x=af[i][0]; vf.y=af[i][1]; vf.z=af[i][2]; vf.w=af[i][3];
        float4 vr; vr.x=ar[i][0]; vr.y=ar[i][1]; vr.z=ar[i][2]; vr.w=ar[i][3];
        *(float4*)&g_Tf[o] = vf;
        *(float4*)&g_Tr[o] = vr;
    }
}

// ------------- K6: elementwise gate fuse -------------------------------------
__global__ __launch_bounds__(256) void k_fuse(float* __restrict__ out)
{
    const size_t idx = ((size_t)blockIdx.x*256 + threadIdx.x)*4;
    const size_t n = (size_t)NM*NHDIM;
    float4 Ff = *(const float4*)&g_FG[0*n + idx];
    float4 Gf = *(const float4*)&g_FG[1*n + idx];
    float4 Fr = *(const float4*)&g_FG[2*n + idx];
    float4 Gr = *(const float4*)&g_FG[3*n + idx];
    float4 o;
    {
        float gf = 1.f/(1.f + __expf(-Gf.x)), gr = 1.f/(1.f + __expf(-Gr.x));
        float wv = 1.f/(1.f + __expf(-(gf - gr)));
        o.x = Ff.x*wv + Fr.x*(1.f - wv);
    }
    {
        float gf = 1.f/(1.f + __expf(-Gf.y)), gr = 1.f/(1.f + __expf(-Gr.y));
        float wv = 1.f/(1.f + __expf(-(gf - gr)));
        o.y = Ff.y*wv + Fr.y*(1.f - wv);
    }
    {
        float gf = 1.f/(1.f + __expf(-Gf.z)), gr = 1.f/(1.f + __expf(-Gr.z));
        float wv = 1.f/(1.f + __expf(-(gf - gr)));
        o.z = Ff.z*wv + Fr.z*(1.f - wv);
    }
    {
        float gf = 1.f/(1.f + __expf(-Gf.w)), gr = 1.f/(1.f + __expf(-Gr.w));
        float wv = 1.f/(1.f + __expf(-(gf - gr)));
        o.w = Ff.w*wv + Fr.w*(1.f - wv);
    }
    *(float4*)&out[idx] = o;
}

// -------------------------------- launch --------------------------------------
extern "C" void kernel_launch(void* const* d_in, const int* in_sizes, int n_in,
                              void* d_out, int out_size)
{
    const float* x   = (const float*)d_in[0];
    const float* Wq  = (const float*)d_in[1];
    const float* bq  = (const float*)d_in[2];
    const float* Wk  = (const float*)d_in[3];
    const float* bk  = (const float*)d_in[4];
    const float* Wv  = (const float*)d_in[5];
    const float* bv  = (const float*)d_in[6];
    const float* cw  = (const float*)d_in[7];
    const float* cb  = (const float*)d_in[8];
    const float* Wfh = (const float*)d_in[9];
    const float* bfh = (const float*)d_in[10];
    const float* Wfg = (const float*)d_in[11];
    const float* bfg = (const float*)d_in[12];
    const float* Wrh = (const float*)d_in[13];
    const float* brh = (const float*)d_in[14];
    const float* Wrg = (const float*)d_in[15];
    const float* brg = (const float*)d_in[16];
    float* out = (float*)d_out;

    k_proj_mma <<<dim3(12, 32), 256>>>(x, Wq, bq, Wk, bk, Wv, bv);
    k_scores   <<<dim3(8, 8, 32), 256>>>();
    k_gate     <<<dim3(1024, 4), 256>>>(cw, cb);
    k_pv       <<<dim3(8, 8, 4), 256>>>();
    k_gemm4_mma<<<dim3(4, 32, 4), 256>>>(Wfh, bfh, Wfg, bfg, Wrh, brh, Wrg, brg);
    k_fuse     <<<2048, 256>>>(out);
}

// round 10
// speedup vs baseline: 3.9193x; 1.4774x over previous
#include <cuda_runtime.h>
#include <cstdint>

#define NB 4
#define NT 1024
#define ND 512
#define NH 8
#define NHD 64
#define NHDIM 512   // NH*NHD
#define NM 4096     // NB*NT

// ---------------- scratch (static device arrays; no allocation) ----------------
__device__ float g_q [NB*NH*NT*NHD];                 // [b,h,t,d]   8 MB
__device__ float g_k [NB*NH*NT*NHD];
__device__ float g_v [NB*NH*NT*NHD];
__device__ float g_At[(size_t)NB*NH*NT*NT];          // raw scores -> E=exp(softmax)
__device__ float g_Rf[(size_t)NB*NT*NT];             // gate pre-activation lin (sign = mask)
__device__ float g_invf[NB*NH*NT];
__device__ float g_invr[NB*NH*NT];
__device__ float g_Tf[NM*NHDIM];                     // [b*t, h*64+d]  8 MB
__device__ float g_Tr[NM*NHDIM];
__device__ float g_FG[4*(size_t)NM*NHDIM];           // Ff|Gf|Fr|Gr pre-act, 32 MB

// ======================= mma.sync tf32 helpers ================================
__device__ __forceinline__ uint32_t f2tf(float f){
    uint32_t r; asm("cvt.rna.tf32.f32 %0, %1;" : "=r"(r) : "f"(f)); return r;
}
__device__ __forceinline__ void mma_tf32(float* c, const uint32_t* a, const uint32_t* b){
    asm volatile("mma.sync.aligned.m16n8k8.row.col.f32.tf32.tf32.f32 "
        "{%0,%1,%2,%3}, {%4,%5,%6,%7}, {%8,%9}, {%0,%1,%2,%3};"
        : "+f"(c[0]), "+f"(c[1]), "+f"(c[2]), "+f"(c[3])
        : "r"(a[0]), "r"(a[1]), "r"(a[2]), "r"(a[3]), "r"(b[0]), "r"(b[1]));
}

#define PA 36    // row pad (floats): frag bank = 4g+t -> conflict-free
#define PB 136   // sB row pad for [k][n] layout in proj/gemm4

// Mainloop: acc[mi][ni][4] += A[m0+.., k] * W[k, n0+..]^T, K=512, both stride 512.
// 256 threads; CTA tile 128x128; warp (wm,wn) tile 64x32.
__device__ __forceinline__ void mma_mainloop(const float* __restrict__ A, int m0,
                                             const float* __restrict__ W, int n0,
                                             float (*sA)[PA], float (*sB)[PB],
                                             float acc[4][4][4],
                                             int tid, int g, int t, int wm, int wn)
{
    for (int c=0; c<16; c++){
#pragma unroll
        for (int i=0;i<4;i++){
            int f = i*256 + tid;
            int r = f>>3, c4 = f&7;
            float4 v = *(const float4*)&A[(size_t)(m0+r)*512 + c*32 + c4*4];
            uint32_t* pa = (uint32_t*)&sA[r][c4*4];
            pa[0]=f2tf(v.x); pa[1]=f2tf(v.y); pa[2]=f2tf(v.z); pa[3]=f2tf(v.w);
        }
#pragma unroll
        for (int i=0;i<4;i++){
            int f = i*256 + tid;
            int kl = f>>5, n4 = f&31;
            float4 v = *(const float4*)&W[(size_t)(c*32+kl)*512 + n0 + n4*4];
            uint32_t* pb = (uint32_t*)&sB[kl][n4*4];
            pb[0]=f2tf(v.x); pb[1]=f2tf(v.y); pb[2]=f2tf(v.z); pb[3]=f2tf(v.w);
        }
        __syncthreads();
#pragma unroll
        for (int kk=0; kk<4; kk++){
            const int k8 = kk*8;
            uint32_t afr[4][4];
#pragma unroll
            for (int mi=0; mi<4; mi++){
                int rb = wm*64 + mi*16;
                afr[mi][0] = __float_as_uint(sA[rb+g  ][k8+t  ]);
                afr[mi][1] = __float_as_uint(sA[rb+g+8][k8+t  ]);
                afr[mi][2] = __float_as_uint(sA[rb+g  ][k8+t+4]);
                afr[mi][3] = __float_as_uint(sA[rb+g+8][k8+t+4]);
            }
            uint32_t bfr[4][2];
#pragma unroll
            for (int ni=0; ni<4; ni++){
                int nb = wn*32 + ni*8 + g;
                bfr[ni][0] = __float_as_uint(sB[k8+t  ][nb]);
                bfr[ni][1] = __float_as_uint(sB[k8+t+4][nb]);
            }
#pragma unroll
            for (int mi=0; mi<4; mi++)
#pragma unroll
                for (int ni=0; ni<4; ni++)
                    mma_tf32(acc[mi][ni], afr[mi], bfr[ni]);
        }
        __syncthreads();
    }
}

// ---------------- K1: QKV projection, tf32 mma --------------------------------
__global__ __launch_bounds__(256) void k_proj_mma(const float* __restrict__ X,
                                                  const float* __restrict__ Wq,
                                                  const float* __restrict__ bq,
                                                  const float* __restrict__ Wk,
                                                  const float* __restrict__ bk,
                                                  const float* __restrict__ Wv,
                                                  const float* __restrict__ bv)
{
    __shared__ float sA[128][PA];
    __shared__ float sB[32][PB];
    const int tid = threadIdx.x, lane = tid&31, warp = tid>>5;
    const int g = lane>>2, t = lane&3;
    const int wm = warp>>2, wn = warp&3;
    const int n0 = blockIdx.x*128, m0 = blockIdx.y*128;
    const int mat = n0>>9, col0 = n0&511;
    const float* W    = (mat==0)?Wq:(mat==1)?Wk:Wv;
    const float* bias = (mat==0)?bq:(mat==1)?bk:bv;
    float* dst        = (mat==0)?g_q:(mat==1)?g_k:g_v;

    float acc[4][4][4];
#pragma unroll
    for (int mi=0;mi<4;mi++)
#pragma unroll
        for (int ni=0;ni<4;ni++)
#pragma unroll
            for (int r=0;r<4;r++) acc[mi][ni][r]=0.f;

    mma_mainloop(X, m0, W, col0, sA, sB, acc, tid, g, t, wm, wn);

#pragma unroll
    for (int mi=0;mi<4;mi++){
#pragma unroll
        for (int ni=0;ni<4;ni++){
            int colb = col0 + wn*32 + ni*8 + 2*t;
            int h = colb>>6, d = colb&63;
            float b0v = bias[colb], b1v = bias[colb+1];
            int r0 = m0 + wm*64 + mi*16 + g;
#pragma unroll
            for (int half=0; half<2; half++){
                int m = r0 + half*8;
                int b = m>>10, tt = m&1023;
                float2 o;
                o.x = acc[mi][ni][half*2+0] + b0v;
                o.y = acc[mi][ni][half*2+1] + b1v;
                *(float2*)&dst[(((size_t)(b*NH+h))*NT + tt)*NHD + d] = o;
            }
        }
    }
}

// ---------------- K5: four output GEMMs, tf32 mma -----------------------------
__global__ __launch_bounds__(256) void k_gemm4_mma(const float* __restrict__ Wfh, const float* __restrict__ bfh,
                                                   const float* __restrict__ Wfg, const float* __restrict__ bfg,
                                                   const float* __restrict__ Wrh, const float* __restrict__ brh,
                                                   const float* __restrict__ Wrg, const float* __restrict__ brg)
{
    __shared__ float sA[128][PA];
    __shared__ float sB[32][PB];
    const int tid = threadIdx.x, lane = tid&31, warp = tid>>5;
    const int g = lane>>2, t = lane&3;
    const int wm = warp>>2, wn = warp&3;
    const int n0 = blockIdx.x*128, m0 = blockIdx.y*128, mat = blockIdx.z;
    const float* A    = (mat<2)? g_Tf : g_Tr;
    const float* W    = (mat==0)?Wfh:(mat==1)?Wfg:(mat==2)?Wrh:Wrg;
    const float* bias = (mat==0)?bfh:(mat==1)?bfg:(mat==2)?brh:brg;
    float* C = g_FG + (size_t)mat*NM*NHDIM;

    float acc[4][4][4];
#pragma unroll
    for (int mi=0;mi<4;mi++)
#pragma unroll
        for (int ni=0;ni<4;ni++)
#pragma unroll
            for (int r=0;r<4;r++) acc[mi][ni][r]=0.f;

    mma_mainloop(A, m0, W, n0, sA, sB, acc, tid, g, t, wm, wn);

#pragma unroll
    for (int mi=0;mi<4;mi++){
#pragma unroll
        for (int ni=0;ni<4;ni++){
            int colb = n0 + wn*32 + ni*8 + 2*t;
            float b0v = bias[colb], b1v = bias[colb+1];
            int r0 = m0 + wm*64 + mi*16 + g;
#pragma unroll
            for (int half=0; half<2; half++){
                int m = r0 + half*8;
                float2 o;
                o.x = acc[mi][ni][half*2+0] + b0v;
                o.y = acc[mi][ni][half*2+1] + b1v;
                *(float2*)&C[(size_t)m*NHDIM + colb] = o;
            }
        }
    }
}

// ---------------- K2: scores via tf32 mma: S = (Q*scale) @ K^T ----------------
// A = Q [q][d] row-major, B = K [t][d] "col-major" per mma -> no transposes.
__global__ __launch_bounds__(256) void k_scores_mma()
{
    __shared__ float sQ[128][PA];
    __shared__ float sK[128][PA];
    const int tid = threadIdx.x, lane = tid&31, warp = tid>>5;
    const int g = lane>>2, t = lane&3;
    const int wm = warp>>2, wn = warp&3;       // wm: 2x64 rows, wn: 4x32 cols
    const int k0 = blockIdx.x*128, q0 = blockIdx.y*128;
    const size_t bh = blockIdx.z;
    const float* Q  = g_q + (bh*NT + (size_t)q0)*NHD;
    const float* Kp = g_k + (bh*NT + (size_t)k0)*NHD;
    float* S = g_At + bh*NT*NT + (size_t)q0*NT + k0;

    float acc[4][4][4];
#pragma unroll
    for (int mi=0;mi<4;mi++)
#pragma unroll
        for (int ni=0;ni<4;ni++)
#pragma unroll
            for (int r=0;r<4;r++) acc[mi][ni][r]=0.f;

#pragma unroll
    for (int c=0; c<2; c++){
#pragma unroll
        for (int i=0;i<4;i++){
            int f = i*256 + tid;
            int r = f>>3, c4 = f&7;
            float4 a = *(const float4*)&Q [(size_t)r*NHD + c*32 + c4*4];
            float4 b = *(const float4*)&Kp[(size_t)r*NHD + c*32 + c4*4];
            uint32_t* pq = (uint32_t*)&sQ[r][c4*4];
            pq[0]=f2tf(a.x*0.125f); pq[1]=f2tf(a.y*0.125f);
            pq[2]=f2tf(a.z*0.125f); pq[3]=f2tf(a.w*0.125f);
            uint32_t* pk = (uint32_t*)&sK[r][c4*4];
            pk[0]=f2tf(b.x); pk[1]=f2tf(b.y); pk[2]=f2tf(b.z); pk[3]=f2tf(b.w);
        }
        __syncthreads();
#pragma unroll
        for (int kk=0; kk<4; kk++){
            const int k8 = kk*8;
            uint32_t afr[4][4];
#pragma unroll
            for (int mi=0; mi<4; mi++){
                int rb = wm*64 + mi*16;
                afr[mi][0] = __float_as_uint(sQ[rb+g  ][k8+t  ]);
                afr[mi][1] = __float_as_uint(sQ[rb+g+8][k8+t  ]);
                afr[mi][2] = __float_as_uint(sQ[rb+g  ][k8+t+4]);
                afr[mi][3] = __float_as_uint(sQ[rb+g+8][k8+t+4]);
            }
            uint32_t bfr[4][2];
#pragma unroll
            for (int ni=0; ni<4; ni++){
                int nb = wn*32 + ni*8 + g;
                bfr[ni][0] = __float_as_uint(sK[nb][k8+t  ]);
                bfr[ni][1] = __float_as_uint(sK[nb][k8+t+4]);
            }
#pragma unroll
            for (int mi=0; mi<4; mi++)
#pragma unroll
                for (int ni=0; ni<4; ni++)
                    mma_tf32(acc[mi][ni], afr[mi], bfr[ni]);
        }
        __syncthreads();
    }
#pragma unroll
    for (int mi=0;mi<4;mi++){
#pragma unroll
        for (int ni=0;ni<4;ni++){
            int col = wn*32 + ni*8 + 2*t;
            int r0 = wm*64 + mi*16 + g;
#pragma unroll
            for (int half=0; half<2; half++){
                float2 o;
                o.x = acc[mi][ni][half*2+0];
                o.y = acc[mi][ni][half*2+1];
                *(float2*)&S[(size_t)(r0+half*8)*NT + col] = o;
            }
        }
    }
}

// ------------- K3: softmax (all heads) + gate + masked denominators -----------
__global__ __launch_bounds__(256) void k_gate(const float* __restrict__ cw,
                                              const float* __restrict__ cbp)
{
    __shared__ float sS[8][1024];
    __shared__ float sInv[8];
    __shared__ float red[8][16];
    const int tid = threadIdx.x;
    const int q = blockIdx.x, b = blockIdx.y;
    const size_t base = ((size_t)(b*NH))*NT*NT + (size_t)q*NT;

#pragma unroll
    for (int i=0;i<8;i++){
        int f = i*256 + tid;
        int h = f>>8, c4 = f&255;
        *(float4*)&sS[h][c4*4] = *(const float4*)&g_At[base + (size_t)h*NT*NT + c4*4];
    }
    __syncthreads();

    const int warp = tid>>5, lane = tid&31;
    {
        float m = -1e30f;
#pragma unroll
        for (int j=0;j<32;j++) m = fmaxf(m, sS[warp][lane + 32*j]);
#pragma unroll
        for (int off=16; off>0; off>>=1) m = fmaxf(m, __shfl_xor_sync(0xffffffffu, m, off));
        float sum = 0.f;
#pragma unroll
        for (int j=0;j<32;j++){
            float e = __expf(sS[warp][lane + 32*j] - m);
            sS[warp][lane + 32*j] = e;
            sum += e;
        }
#pragma unroll
        for (int off=16; off>0; off>>=1) sum += __shfl_xor_sync(0xffffffffu, sum, off);
        if (lane==0) sInv[warp] = 1.0f/sum;
    }
    __syncthreads();

    float w[NH];
#pragma unroll
    for (int h=0;h<NH;h++) w[h]=cw[h];
    const float cb = cbp[0];
    float inv[NH];
#pragma unroll
    for (int h=0;h<NH;h++) inv[h]=sInv[h];

    float denf[NH], denr[NH];
#pragma unroll
    for (int h=0;h<NH;h++){ denf[h]=0.f; denr[h]=0.f; }
    float* lin_out = g_Rf + ((size_t)b*NT + q)*NT;

#pragma unroll
    for (int kk=0; kk<4; kk++){
        int k = kk*256 + tid;
        float A[NH];
        float lin = cb;
#pragma unroll
        for (int h=0;h<NH;h++){ A[h] = sS[h][k]*inv[h]; lin = fmaf(w[h], A[h], lin); }
        lin_out[k] = lin;
        bool bf = (lin <= 0.f);
        bool br = (lin >= 0.f);
#pragma unroll
        for (int h=0;h<NH;h++){
            float E = __expf(A[h]);
            g_At[base + (size_t)h*NT*NT + k] = E;
            denf[h] += bf ? E : 1.0f;
            denr[h] += br ? E : 1.0f;
        }
    }
#pragma unroll
    for (int v=0; v<16; v++){
        float val = (v<8)? denf[v] : denr[v-8];
#pragma unroll
        for (int off=16; off>0; off>>=1) val += __shfl_down_sync(0xffffffffu, val, off);
        if (lane==0) red[warp][v]=val;
    }
    __syncthreads();
    if (tid < 16){
        float s=0.f;
#pragma unroll
        for (int wp=0; wp<8; wp++) s += red[wp][tid];
        int h = tid & 7;
        float is = 1.0f/s;
        if (tid < 8) g_invf[((size_t)(b*NH+h))*NT + q] = is;
        else         g_invr[((size_t)(b*NH+h))*NT + q] = is;
    }
}

// ------------- K4: PV via tf32 mma. A = [Pf;Pr] stacked 256x32, B = V^T -------
__global__ __launch_bounds__(256) void k_pv_mma()
{
    __shared__ float sA[256][PA];    // rows 0-127: Pf, 128-255: Pr
    __shared__ float sB[64][PA];     // V^T: [d][k]
    __shared__ float sInvF[128], sInvR[128];
    const int tid = threadIdx.x, lane = tid&31, warp = tid>>5;
    const int g = lane>>2, t = lane&3;
    const int wm = warp>>1, wn = warp&1;       // wm: 4x64 rows, wn: 2x32 d-cols
    const int qt=blockIdx.x, h=blockIdx.y, b=blockIdx.z;
    const int q0 = qt*128;
    const size_t bh = (size_t)(b*NH+h);
    const float* E = g_At + bh*NT*NT + (size_t)q0*NT;
    const float* L = g_Rf + ((size_t)b*NT + q0)*NT;
    const float* V = g_v  + bh*NT*NHD;
    if (tid<128){
        sInvF[tid]=g_invf[bh*NT+q0+tid];
        sInvR[tid]=g_invr[bh*NT+q0+tid];
    }
    __syncthreads();

    float acc[4][4][4];
#pragma unroll
    for (int mi=0;mi<4;mi++)
#pragma unroll
        for (int ni=0;ni<4;ni++)
#pragma unroll
            for (int r=0;r<4;r++) acc[mi][ni][r]=0.f;

    for (int c=0; c<32; c++){
        const int k0c = c*32;
        // build P tiles (tf32) from stored E and gate sign L
#pragma unroll
        for (int i=0;i<4;i++){
            int f = i*256 + tid;
            int qq = f>>3, k4 = f&7;
            float4 e = *(const float4*)&E[(size_t)qq*NT + k0c + k4*4];
            float4 l = *(const float4*)&L[(size_t)qq*NT + k0c + k4*4];
            float invf = sInvF[qq], invr = sInvR[qq];
            uint32_t* pf = (uint32_t*)&sA[qq    ][k4*4];
            uint32_t* pr = (uint32_t*)&sA[128+qq][k4*4];
            pf[0]=f2tf(((l.x<=0.f)? e.x : 1.f)*invf);
            pf[1]=f2tf(((l.y<=0.f)? e.y : 1.f)*invf);
            pf[2]=f2tf(((l.z<=0.f)? e.z : 1.f)*invf);
            pf[3]=f2tf(((l.w<=0.f)? e.w : 1.f)*invf);
            pr[0]=f2tf(((l.x>=0.f)? e.x : 1.f)*invr);
            pr[1]=f2tf(((l.y>=0.f)? e.y : 1.f)*invr);
            pr[2]=f2tf(((l.z>=0.f)? e.z : 1.f)*invr);
            pr[3]=f2tf(((l.w>=0.f)? e.w : 1.f)*invr);
        }
        // V^T tile: [64 d][32 k]
#pragma unroll
        for (int i=0;i<2;i++){
            int f = i*256 + tid;
            int kl = f>>4, d4 = f&15;
            float4 v = *(const float4*)&V[(size_t)(k0c+kl)*NHD + d4*4];
            sB[d4*4+0][kl] = __uint_as_float(f2tf(v.x));
            sB[d4*4+1][kl] = __uint_as_float(f2tf(v.y));
            sB[d4*4+2][kl] = __uint_as_float(f2tf(v.z));
            sB[d4*4+3][kl] = __uint_as_float(f2tf(v.w));
        }
        __syncthreads();
#pragma unroll
        for (int kk=0; kk<4; kk++){
            const int k8 = kk*8;
            uint32_t afr[4][4];
#pragma unroll
            for (int mi=0; mi<4; mi++){
                int rb = wm*64 + mi*16;
                afr[mi][0] = __float_as_uint(sA[rb+g  ][k8+t  ]);
                afr[mi][1] = __float_as_uint(sA[rb+g+8][k8+t  ]);
                afr[mi][2] = __float_as_uint(sA[rb+g  ][k8+t+4]);
                afr[mi][3] = __float_as_uint(sA[rb+g+8][k8+t+4]);
            }
            uint32_t bfr[4][2];
#pragma unroll
            for (int ni=0; ni<4; ni++){
                int nb = wn*32 + ni*8 + g;
                bfr[ni][0] = __float_as_uint(sB[nb][k8+t  ]);
                bfr[ni][1] = __float_as_uint(sB[nb][k8+t+4]);
            }
#pragma unroll
            for (int mi=0; mi<4; mi++)
#pragma unroll
                for (int ni=0; ni<4; ni++)
                    mma_tf32(acc[mi][ni], afr[mi], bfr[ni]);
        }
        __syncthreads();
    }
    // epilogue: rows <128 -> g_Tf, rows >=128 -> g_Tr
#pragma unroll
    for (int mi=0;mi<4;mi++){
#pragma unroll
        for (int ni=0;ni<4;ni++){
            int col = wn*32 + ni*8 + 2*t;     // d index 0..63
            int r0 = wm*64 + mi*16 + g;
#pragma unroll
            for (int half=0; half<2; half++){
                int rr = r0 + half*8;
                float* dst = (rr < 128) ? g_Tf : g_Tr;
                int q = q0 + (rr & 127);
                float2 o;
                o.x = acc[mi][ni][half*2+0];
                o.y = acc[mi][ni][half*2+1];
                *(float2*)&dst[((size_t)b*NT + q)*NHDIM + h*NHD + col] = o;
            }
        }
    }
}

// ------------- K6: elementwise gate fuse -------------------------------------
__global__ __launch_bounds__(256) void k_fuse(float* __restrict__ out)
{
    const size_t idx = ((size_t)blockIdx.x*256 + threadIdx.x)*4;
    const size_t n = (size_t)NM*NHDIM;
    float4 Ff = *(const float4*)&g_FG[0*n + idx];
    float4 Gf = *(const float4*)&g_FG[1*n + idx];
    float4 Fr = *(const float4*)&g_FG[2*n + idx];
    float4 Gr = *(const float4*)&g_FG[3*n + idx];
    float4 o;
    {
        float gf = 1.f/(1.f + __expf(-Gf.x)), gr = 1.f/(1.f + __expf(-Gr.x));
        float wv = 1.f/(1.f + __expf(-(gf - gr)));
        o.x = Ff.x*wv + Fr.x*(1.f - wv);
    }
    {
        float gf = 1.f/(1.f + __expf(-Gf.y)), gr = 1.f/(1.f + __expf(-Gr.y));
        float wv = 1.f/(1.f + __expf(-(gf - gr)));
        o.y = Ff.y*wv + Fr.y*(1.f - wv);
    }
    {
        float gf = 1.f/(1.f + __expf(-Gf.z)), gr = 1.f/(1.f + __expf(-Gr.z));
        float wv = 1.f/(1.f + __expf(-(gf - gr)));
        o.z = Ff.z*wv + Fr.z*(1.f - wv);
    }
    {
        float gf = 1.f/(1.f + __expf(-Gf.w)), gr = 1.f/(1.f + __expf(-Gr.w));
        float wv = 1.f/(1.f + __expf(-(gf - gr)));
        o.w = Ff.w*wv + Fr.w*(1.f - wv);
    }
    *(float4*)&out[idx] = o;
}

// -------------------------------- launch --------------------------------------
extern "C" void kernel_launch(void* const* d_in, const int* in_sizes, int n_in,
                              void* d_out, int out_size)
{
    const float* x   = (const float*)d_in[0];
    const float* Wq  = (const float*)d_in[1];
    const float* bq  = (const float*)d_in[2];
    const float* Wk  = (const float*)d_in[3];
    const float* bk  = (const float*)d_in[4];
    const float* Wv  = (const float*)d_in[5];
    const float* bv  = (const float*)d_in[6];
    const float* cw  = (const float*)d_in[7];
    const float* cb  = (const float*)d_in[8];
    const float* Wfh = (const float*)d_in[9];
    const float* bfh = (const float*)d_in[10];
    const float* Wfg = (const float*)d_in[11];
    const float* bfg = (const float*)d_in[12];
    const float* Wrh = (const float*)d_in[13];
    const float* brh = (const float*)d_in[14];
    const float* Wrg = (const float*)d_in[15];
    const float* brg = (const float*)d_in[16];
    float* out = (float*)d_out;

    k_proj_mma  <<<dim3(12, 32), 256>>>(x, Wq, bq, Wk, bk, Wv, bv);
    k_scores_mma<<<dim3(8, 8, 32), 256>>>();
    k_gate      <<<dim3(1024, 4), 256>>>(cw, cb);
    k_pv_mma    <<<dim3(8, 8, 4), 256>>>();
    k_gemm4_mma <<<dim3(4, 32, 4), 256>>>(Wfh, bfh, Wfg, bfg, Wrh, brh, Wrg, brg);
    k_fuse      <<<2048, 256>>>(out);
}

// round 13
// speedup vs baseline: 4.0715x; 1.0388x over previous
#include <cuda_runtime.h>
#include <cuda_fp16.h>
#include <cstdint>

#define NB 4
#define NT 1024
#define ND 512
#define NH 8
#define NHD 64
#define NHDIM 512   // NH*NHD
#define NM 4096     // NB*NT

// ---------------- scratch (static device arrays; no allocation) ----------------
__device__ float g_q [NB*NH*NT*NHD];                 // [b,h,t,d]   8 MB
__device__ float g_k [NB*NH*NT*NHD];
__device__ float g_v [NB*NH*NT*NHD];
__device__ float g_At[(size_t)NB*NH*NT*NT];          // raw scaled scores S
__device__ __half g_Pf[(size_t)NB*NH*NT*NT];         // masked-normalized P (fwd), fp16
__device__ __half g_Pr[(size_t)NB*NH*NT*NT];         // masked-normalized P (rev), fp16
__device__ float g_Tf[NM*NHDIM];                     // [b*t, h*64+d]  8 MB
__device__ float g_Tr[NM*NHDIM];
__device__ float g_FG[4*(size_t)NM*NHDIM];           // Ff|Gf|Fr|Gr pre-act, 32 MB

// ======================= mma helpers ================================
__device__ __forceinline__ uint32_t f2tf(float f){
    uint32_t r; asm("cvt.rna.tf32.f32 %0, %1;" : "=r"(r) : "f"(f)); return r;
}
__device__ __forceinline__ void mma_tf32(float* c, const uint32_t* a, const uint32_t* b){
    asm volatile("mma.sync.aligned.m16n8k8.row.col.f32.tf32.tf32.f32 "
        "{%0,%1,%2,%3}, {%4,%5,%6,%7}, {%8,%9}, {%0,%1,%2,%3};"
        : "+f"(c[0]), "+f"(c[1]), "+f"(c[2]), "+f"(c[3])
        : "r"(a[0]), "r"(a[1]), "r"(a[2]), "r"(a[3]), "r"(b[0]), "r"(b[1]));
}
__device__ __forceinline__ void mma_f16(float* c, const uint32_t* a, const uint32_t* b){
    asm volatile("mma.sync.aligned.m16n8k16.row.col.f32.f16.f16.f32 "
        "{%0,%1,%2,%3}, {%4,%5,%6,%7}, {%8,%9}, {%0,%1,%2,%3};"
        : "+f"(c[0]), "+f"(c[1]), "+f"(c[2]), "+f"(c[3])
        : "r"(a[0]), "r"(a[1]), "r"(a[2]), "r"(a[3]), "r"(b[0]), "r"(b[1]));
}

#define PA 36    // fp32 row pad: frag bank = 4g+t -> conflict-free
#define PB 136
#define PH 40    // fp16 row pad (halves): stride 20 words -> g*20+t conflict-free

// Mainloop: acc[mi][ni][4] += A[m0+.., k] * W[k, n0+..]^T, K=512, both stride 512.
__device__ __forceinline__ void mma_mainloop(const float* __restrict__ A, int m0,
                                             const float* __restrict__ W, int n0,
                                             float (*sA)[PA], float (*sB)[PB],
                                             float acc[4][4][4],
                                             int tid, int g, int t, int wm, int wn)
{
    for (int c=0; c<16; c++){
#pragma unroll
        for (int i=0;i<4;i++){
            int f = i*256 + tid;
            int r = f>>3, c4 = f&7;
            float4 v = *(const float4*)&A[(size_t)(m0+r)*512 + c*32 + c4*4];
            uint32_t* pa = (uint32_t*)&sA[r][c4*4];
            pa[0]=f2tf(v.x); pa[1]=f2tf(v.y); pa[2]=f2tf(v.z); pa[3]=f2tf(v.w);
        }
#pragma unroll
        for (int i=0;i<4;i++){
            int f = i*256 + tid;
            int kl = f>>5, n4 = f&31;
            float4 v = *(const float4*)&W[(size_t)(c*32+kl)*512 + n0 + n4*4];
            uint32_t* pb = (uint32_t*)&sB[kl][n4*4];
            pb[0]=f2tf(v.x); pb[1]=f2tf(v.y); pb[2]=f2tf(v.z); pb[3]=f2tf(v.w);
        }
        __syncthreads();
#pragma unroll
        for (int kk=0; kk<4; kk++){
            const int k8 = kk*8;
            uint32_t afr[4][4];
#pragma unroll
            for (int mi=0; mi<4; mi++){
                int rb = wm*64 + mi*16;
                afr[mi][0] = __float_as_uint(sA[rb+g  ][k8+t  ]);
                afr[mi][1] = __float_as_uint(sA[rb+g+8][k8+t  ]);
                afr[mi][2] = __float_as_uint(sA[rb+g  ][k8+t+4]);
                afr[mi][3] = __float_as_uint(sA[rb+g+8][k8+t+4]);
            }
            uint32_t bfr[4][2];
#pragma unroll
            for (int ni=0; ni<4; ni++){
                int nb = wn*32 + ni*8 + g;
                bfr[ni][0] = __float_as_uint(sB[k8+t  ][nb]);
                bfr[ni][1] = __float_as_uint(sB[k8+t+4][nb]);
            }
#pragma unroll
            for (int mi=0; mi<4; mi++)
#pragma unroll
                for (int ni=0; ni<4; ni++)
                    mma_tf32(acc[mi][ni], afr[mi], bfr[ni]);
        }
        __syncthreads();
    }
}

// ---------------- K1: QKV projection, tf32 mma --------------------------------
__global__ __launch_bounds__(256) void k_proj_mma(const float* __restrict__ X,
                                                  const float* __restrict__ Wq,
                                                  const float* __restrict__ bq,
                                                  const float* __restrict__ Wk,
                                                  const float* __restrict__ bk,
                                                  const float* __restrict__ Wv,
                                                  const float* __restrict__ bv)
{
    __shared__ float sA[128][PA];
    __shared__ float sB[32][PB];
    const int tid = threadIdx.x, lane = tid&31, warp = tid>>5;
    const int g = lane>>2, t = lane&3;
    const int wm = warp>>2, wn = warp&3;
    const int n0 = blockIdx.x*128, m0 = blockIdx.y*128;
    const int mat = n0>>9, col0 = n0&511;
    const float* W    = (mat==0)?Wq:(mat==1)?Wk:Wv;
    const float* bias = (mat==0)?bq:(mat==1)?bk:bv;
    float* dst        = (mat==0)?g_q:(mat==1)?g_k:g_v;

    float acc[4][4][4];
#pragma unroll
    for (int mi=0;mi<4;mi++)
#pragma unroll
        for (int ni=0;ni<4;ni++)
#pragma unroll
            for (int r=0;r<4;r++) acc[mi][ni][r]=0.f;

    mma_mainloop(X, m0, W, col0, sA, sB, acc, tid, g, t, wm, wn);

#pragma unroll
    for (int mi=0;mi<4;mi++){
#pragma unroll
        for (int ni=0;ni<4;ni++){
            int colb = col0 + wn*32 + ni*8 + 2*t;
            int h = colb>>6, d = colb&63;
            float b0v = bias[colb], b1v = bias[colb+1];
            int r0 = m0 + wm*64 + mi*16 + g;
#pragma unroll
            for (int half=0; half<2; half++){
                int m = r0 + half*8;
                int b = m>>10, tt = m&1023;
                float2 o;
                o.x = acc[mi][ni][half*2+0] + b0v;
                o.y = acc[mi][ni][half*2+1] + b1v;
                *(float2*)&dst[(((size_t)(b*NH+h))*NT + tt)*NHD + d] = o;
            }
        }
    }
}

// ---------------- K5: four output GEMMs, tf32 mma -----------------------------
__global__ __launch_bounds__(256) void k_gemm4_mma(const float* __restrict__ Wfh, const float* __restrict__ bfh,
                                                   const float* __restrict__ Wfg, const float* __restrict__ bfg,
                                                   const float* __restrict__ Wrh, const float* __restrict__ brh,
                                                   const float* __restrict__ Wrg, const float* __restrict__ brg)
{
    __shared__ float sA[128][PA];
    __shared__ float sB[32][PB];
    const int tid = threadIdx.x, lane = tid&31, warp = tid>>5;
    const int g = lane>>2, t = lane&3;
    const int wm = warp>>2, wn = warp&3;
    const int n0 = blockIdx.x*128, m0 = blockIdx.y*128, mat = blockIdx.z;
    const float* A    = (mat<2)? g_Tf : g_Tr;
    const float* W    = (mat==0)?Wfh:(mat==1)?Wfg:(mat==2)?Wrh:Wrg;
    const float* bias = (mat==0)?bfh:(mat==1)?bfg:(mat==2)?brh:brg;
    float* C = g_FG + (size_t)mat*NM*NHDIM;

    float acc[4][4][4];
#pragma unroll
    for (int mi=0;mi<4;mi++)
#pragma unroll
        for (int ni=0;ni<4;ni++)
#pragma unroll
            for (int r=0;r<4;r++) acc[mi][ni][r]=0.f;

    mma_mainloop(A, m0, W, n0, sA, sB, acc, tid, g, t, wm, wn);

#pragma unroll
    for (int mi=0;mi<4;mi++){
#pragma unroll
        for (int ni=0;ni<4;ni++){
            int colb = n0 + wn*32 + ni*8 + 2*t;
            float b0v = bias[colb], b1v = bias[colb+1];
            int r0 = m0 + wm*64 + mi*16 + g;
#pragma unroll
            for (int half=0; half<2; half++){
                int m = r0 + half*8;
                float2 o;
                o.x = acc[mi][ni][half*2+0] + b0v;
                o.y = acc[mi][ni][half*2+1] + b1v;
                *(float2*)&C[(size_t)m*NHDIM + colb] = o;
            }
        }
    }
}

// ---------------- K2: scores via tf32 mma: S = (Q*scale) @ K^T ----------------
__global__ __launch_bounds__(256) void k_scores_mma()
{
    __shared__ float sQ[128][PA];
    __shared__ float sK[128][PA];
    const int tid = threadIdx.x, lane = tid&31, warp = tid>>5;
    const int g = lane>>2, t = lane&3;
    const int wm = warp>>2, wn = warp&3;
    const int k0 = blockIdx.x*128, q0 = blockIdx.y*128;
    const size_t bh = blockIdx.z;
    const float* Q  = g_q + (bh*NT + (size_t)q0)*NHD;
    const float* Kp = g_k + (bh*NT + (size_t)k0)*NHD;
    float* S = g_At + bh*NT*NT + (size_t)q0*NT + k0;

    float acc[4][4][4];
#pragma unroll
    for (int mi=0;mi<4;mi++)
#pragma unroll
        for (int ni=0;ni<4;ni++)
#pragma unroll
            for (int r=0;r<4;r++) acc[mi][ni][r]=0.f;

#pragma unroll
    for (int c=0; c<2; c++){
#pragma unroll
        for (int i=0;i<4;i++){
            int f = i*256 + tid;
            int r = f>>3, c4 = f&7;
            float4 a = *(const float4*)&Q [(size_t)r*NHD + c*32 + c4*4];
            float4 b = *(const float4*)&Kp[(size_t)r*NHD + c*32 + c4*4];
            uint32_t* pq = (uint32_t*)&sQ[r][c4*4];
            pq[0]=f2tf(a.x*0.125f); pq[1]=f2tf(a.y*0.125f);
            pq[2]=f2tf(a.z*0.125f); pq[3]=f2tf(a.w*0.125f);
            uint32_t* pk = (uint32_t*)&sK[r][c4*4];
            pk[0]=f2tf(b.x); pk[1]=f2tf(b.y); pk[2]=f2tf(b.z); pk[3]=f2tf(b.w);
        }
        __syncthreads();
#pragma unroll
        for (int kk=0; kk<4; kk++){
            const int k8 = kk*8;
            uint32_t afr[4][4];
#pragma unroll
            for (int mi=0; mi<4; mi++){
                int rb = wm*64 + mi*16;
                afr[mi][0] = __float_as_uint(sQ[rb+g  ][k8+t  ]);
                afr[mi][1] = __float_as_uint(sQ[rb+g+8][k8+t  ]);
                afr[mi][2] = __float_as_uint(sQ[rb+g  ][k8+t+4]);
                afr[mi][3] = __float_as_uint(sQ[rb+g+8][k8+t+4]);
            }
            uint32_t bfr[4][2];
#pragma unroll
            for (int ni=0; ni<4; ni++){
                int nb = wn*32 + ni*8 + g;
                bfr[ni][0] = __float_as_uint(sK[nb][k8+t  ]);
                bfr[ni][1] = __float_as_uint(sK[nb][k8+t+4]);
            }
#pragma unroll
            for (int mi=0; mi<4; mi++)
#pragma unroll
                for (int ni=0; ni<4; ni++)
                    mma_tf32(acc[mi][ni], afr[mi], bfr[ni]);
        }
        __syncthreads();
    }
#pragma unroll
    for (int mi=0;mi<4;mi++){
#pragma unroll
        for (int ni=0;ni<4;ni++){
            int col = wn*32 + ni*8 + 2*t;
            int r0 = wm*64 + mi*16 + g;
#pragma unroll
            for (int half=0; half<2; half++){
                float2 o;
                o.x = acc[mi][ni][half*2+0];
                o.y = acc[mi][ni][half*2+1];
                *(float2*)&S[(size_t)(r0+half*8)*NT + col] = o;
            }
        }
    }
}

// ------------- K3: softmax + gate + masks -> fp16 Pf/Pr ----------------------
__global__ __launch_bounds__(256) void k_gate(const float* __restrict__ cw,
                                              const float* __restrict__ cbp)
{
    __shared__ float sS[8][1024];
    __shared__ float sInv[8];
    __shared__ float red[8][16];
    __shared__ float sIf[8], sIr[8];
    const int tid = threadIdx.x;
    const int q = blockIdx.x, b = blockIdx.y;
    const size_t base = ((size_t)(b*NH))*NT*NT + (size_t)q*NT;

#pragma unroll
    for (int i=0;i<8;i++){
        int f = i*256 + tid;
        int h = f>>8, c4 = f&255;
        *(float4*)&sS[h][c4*4] = *(const float4*)&g_At[base + (size_t)h*NT*NT + c4*4];
    }
    __syncthreads();

    const int warp = tid>>5, lane = tid&31;
    {
        float m = -1e30f;
#pragma unroll
        for (int j=0;j<32;j++) m = fmaxf(m, sS[warp][lane + 32*j]);
#pragma unroll
        for (int off=16; off>0; off>>=1) m = fmaxf(m, __shfl_xor_sync(0xffffffffu, m, off));
        float sum = 0.f;
#pragma unroll
        for (int j=0;j<32;j++){
            float e = __expf(sS[warp][lane + 32*j] - m);
            sS[warp][lane + 32*j] = e;
            sum += e;
        }
#pragma unroll
        for (int off=16; off>0; off>>=1) sum += __shfl_xor_sync(0xffffffffu, sum, off);
        if (lane==0) sInv[warp] = 1.0f/sum;
    }
    __syncthreads();

    float w[NH];
#pragma unroll
    for (int h=0;h<NH;h++) w[h]=cw[h];
    const float cb = cbp[0];
    float inv[NH];
#pragma unroll
    for (int h=0;h<NH;h++) inv[h]=sInv[h];

    float denf[NH], denr[NH];
#pragma unroll
    for (int h=0;h<NH;h++){ denf[h]=0.f; denr[h]=0.f; }
    float linv[2][2];

    // pass 1: A_t, lin, E=exp(A_t) back into sS, masked denominators
#pragma unroll
    for (int kk=0; kk<2; kk++){
#pragma unroll
        for (int j=0; j<2; j++){
            int k = kk*512 + tid*2 + j;
            float A[NH];
            float lin = cb;
#pragma unroll
            for (int h=0;h<NH;h++){ A[h] = sS[h][k]*inv[h]; lin = fmaf(w[h], A[h], lin); }
            linv[kk][j] = lin;
            bool bf = (lin <= 0.f);
            bool br = (lin >= 0.f);
#pragma unroll
            for (int h=0;h<NH;h++){
                float E = __expf(A[h]);
                sS[h][k] = E;
                denf[h] += bf ? E : 1.0f;
                denr[h] += br ? E : 1.0f;
            }
        }
    }
    // block reduction of 16 values
#pragma unroll
    for (int v=0; v<16; v++){
        float val = (v<8)? denf[v] : denr[v-8];
#pragma unroll
        for (int off=16; off>0; off>>=1) val += __shfl_down_sync(0xffffffffu, val, off);
        if (lane==0) red[warp][v]=val;
    }
    __syncthreads();
    if (tid < 16){
        float s=0.f;
#pragma unroll
        for (int wp=0; wp<8; wp++) s += red[wp][tid];
        float is = 1.0f/s;
        if (tid < 8) sIf[tid] = is;
        else         sIr[tid-8] = is;
    }
    __syncthreads();

    // pass 2: emit fp16 Pf/Pr (coalesced half2 stores)
#pragma unroll
    for (int kk=0; kk<2; kk++){
        int k = kk*512 + tid*2;
        float lin0 = linv[kk][0], lin1 = linv[kk][1];
        bool bf0 = (lin0 <= 0.f), bf1 = (lin1 <= 0.f);
        bool br0 = (lin0 >= 0.f), br1 = (lin1 >= 0.f);
#pragma unroll
        for (int h=0;h<NH;h++){
            float E0 = sS[h][k], E1 = sS[h][k+1];
            float fi = sIf[h], ri = sIr[h];
            __half2 pf = __floats2half2_rn((bf0? E0 : 1.0f)*fi, (bf1? E1 : 1.0f)*fi);
            __half2 pr = __floats2half2_rn((br0? E0 : 1.0f)*ri, (br1? E1 : 1.0f)*ri);
            size_t o = base + (size_t)h*NT*NT + k;
            *(__half2*)&g_Pf[o] = pf;
            *(__half2*)&g_Pr[o] = pr;
        }
    }
}

// ------------- K4: PV via fp16 mma. A = [Pf;Pr] stacked 256x32 ---------------
__global__ __launch_bounds__(256) void k_pv_mma()
{
    __shared__ __half sA[256][PH];    // rows 0-127: Pf, 128-255: Pr
    __shared__ __half sB[64][PH];     // V^T: [d][k] fp16
    const int tid = threadIdx.x, lane = tid&31, warp = tid>>5;
    const int g = lane>>2, t = lane&3;
    const int wm = warp>>1, wn = warp&1;       // wm: 4x64 rows, wn: 2x32 d-cols
    const int qt=blockIdx.x, h=blockIdx.y, b=blockIdx.z;
    const int q0 = qt*128;
    const size_t bh = (size_t)(b*NH+h);
    const __half* Pf = g_Pf + (bh*NT + (size_t)q0)*NT;
    const __half* Pr = g_Pr + (bh*NT + (size_t)q0)*NT;
    const float* V = g_v + bh*NT*NHD;

    float acc[4][4][4];
#pragma unroll
    for (int mi=0;mi<4;mi++)
#pragma unroll
        for (int ni=0;ni<4;ni++)
#pragma unroll
            for (int r=0;r<4;r++) acc[mi][ni][r]=0.f;

    for (int c=0; c<32; c++){
        const int k0c = c*32;
        // A tiles: direct fp16 copies (8 halves per uint4)
#pragma unroll
        for (int i=0;i<2;i++){
            int f = i*256 + tid;
            int qq = f>>2, k8 = f&3;
            *(uint4*)&sA[qq    ][k8*8] = *(const uint4*)&Pf[(size_t)qq*NT + k0c + k8*8];
            *(uint4*)&sA[128+qq][k8*8] = *(const uint4*)&Pr[(size_t)qq*NT + k0c + k8*8];
        }
        // B tile: V^T [64 d][32 k], cvt fp32 -> fp16
        {
            int kl = tid>>3, d8 = tid&7;
            const float* vr = &V[(size_t)(k0c+kl)*NHD + d8*8];
            float4 v0 = *(const float4*)&vr[0];
            float4 v1 = *(const float4*)&vr[4];
            sB[d8*8+0][kl]=__float2half_rn(v0.x); sB[d8*8+1][kl]=__float2half_rn(v0.y);
            sB[d8*8+2][kl]=__float2half_rn(v0.z); sB[d8*8+3][kl]=__float2half_rn(v0.w);
            sB[d8*8+4][kl]=__float2half_rn(v1.x); sB[d8*8+5][kl]=__float2half_rn(v1.y);
            sB[d8*8+6][kl]=__float2half_rn(v1.z); sB[d8*8+7][kl]=__float2half_rn(v1.w);
        }
        __syncthreads();
#pragma unroll
        for (int kk=0; kk<2; kk++){
            const int k16 = kk*16;
            uint32_t afr[4][4];
#pragma unroll
            for (int mi=0; mi<4; mi++){
                int rb = wm*64 + mi*16;
                afr[mi][0] = *(uint32_t*)&sA[rb+g  ][k16 + 2*t    ];
                afr[mi][1] = *(uint32_t*)&sA[rb+g+8][k16 + 2*t    ];
                afr[mi][2] = *(uint32_t*)&sA[rb+g  ][k16 + 2*t + 8];
                afr[mi][3] = *(uint32_t*)&sA[rb+g+8][k16 + 2*t + 8];
            }
            uint32_t bfr[4][2];
#pragma unroll
            for (int ni=0; ni<4; ni++){
                int nb = wn*32 + ni*8 + g;
                bfr[ni][0] = *(uint32_t*)&sB[nb][k16 + 2*t    ];
                bfr[ni][1] = *(uint32_t*)&sB[nb][k16 + 2*t + 8];
            }
#pragma unroll
            for (int mi=0; mi<4; mi++)
#pragma unroll
                for (int ni=0; ni<4; ni++)
                    mma_f16(acc[mi][ni], afr[mi], bfr[ni]);
        }
        __syncthreads();
    }
    // epilogue: rows <128 -> g_Tf, rows >=128 -> g_Tr
#pragma unroll
    for (int mi=0;mi<4;mi++){
#pragma unroll
        for (int ni=0;ni<4;ni++){
            int col = wn*32 + ni*8 + 2*t;
            int r0 = wm*64 + mi*16 + g;
#pragma unroll
            for (int half=0; half<2; half++){
                int rr = r0 + half*8;
                float* dst = (rr < 128) ? g_Tf : g_Tr;
                int q = q0 + (rr & 127);
                float2 o;
                o.x = acc[mi][ni][half*2+0];
                o.y = acc[mi][ni][half*2+1];
                *(float2*)&dst[((size_t)b*NT + q)*NHDIM + h*NHD + col] = o;
            }
        }
    }
}

// ------------- K6: elementwise gate fuse -------------------------------------
__global__ __launch_bounds__(256) void k_fuse(float* __restrict__ out)
{
    const size_t idx = ((size_t)blockIdx.x*256 + threadIdx.x)*4;
    const size_t n = (size_t)NM*NHDIM;
    float4 Ff = *(const float4*)&g_FG[0*n + idx];
    float4 Gf = *(const float4*)&g_FG[1*n + idx];
    float4 Fr = *(const float4*)&g_FG[2*n + idx];
    float4 Gr = *(const float4*)&g_FG[3*n + idx];
    float4 o;
    {
        float gf = 1.f/(1.f + __expf(-Gf.x)), gr = 1.f/(1.f + __expf(-Gr.x));
        float wv = 1.f/(1.f + __expf(-(gf - gr)));
        o.x = Ff.x*wv + Fr.x*(1.f - wv);
    }
    {
        float gf = 1.f/(1.f + __expf(-Gf.y)), gr = 1.f/(1.f + __expf(-Gr.y));
        float wv = 1.f/(1.f + __expf(-(gf - gr)));
        o.y = Ff.y*wv + Fr.y*(1.f - wv);
    }
    {
        float gf = 1.f/(1.f + __expf(-Gf.z)), gr = 1.f/(1.f + __expf(-Gr.z));
        float wv = 1.f/(1.f + __expf(-(gf - gr)));
        o.z = Ff.z*wv + Fr.z*(1.f - wv);
    }
    {
        float gf = 1.f/(1.f + __expf(-Gf.w)), gr = 1.f/(1.f + __expf(-Gr.w));
        float wv = 1.f/(1.f + __expf(-(gf - gr)));
        o.w = Ff.w*wv + Fr.w*(1.f - wv);
    }
    *(float4*)&out[idx] = o;
}

// -------------------------------- launch --------------------------------------
extern "C" void kernel_launch(void* const* d_in, const int* in_sizes, int n_in,
                              void* d_out, int out_size)
{
    const float* x   = (const float*)d_in[0];
    const float* Wq  = (const float*)d_in[1];
    const float* bq  = (const float*)d_in[2];
    const float* Wk  = (const float*)d_in[3];
    const float* bk  = (const float*)d_in[4];
    const float* Wv  = (const float*)d_in[5];
    const float* bv  = (const float*)d_in[6];
    const float* cw  = (const float*)d_in[7];
    const float* cb  = (const float*)d_in[8];
    const float* Wfh = (const float*)d_in[9];
    const float* bfh = (const float*)d_in[10];
    const float* Wfg = (const float*)d_in[11];
    const float* bfg = (const float*)d_in[12];
    const float* Wrh = (const float*)d_in[13];
    const float* brh = (const float*)d_in[14];
    const float* Wrg = (const float*)d_in[15];
    const float* brg = (const float*)d_in[16];
    float* out = (float*)d_out;

    k_proj_mma  <<<dim3(12, 32), 256>>>(x, Wq, bq, Wk, bk, Wv, bv);
    k_scores_mma<<<dim3(8, 8, 32), 256>>>();
    k_gate      <<<dim3(1024, 4), 256>>>(cw, cb);
    k_pv_mma    <<<dim3(8, 8, 4), 256>>>();
    k_gemm4_mma <<<dim3(4, 32, 4), 256>>>(Wfh, bfh, Wfg, bfg, Wrh, brh, Wrg, brg);
    k_fuse      <<<2048, 256>>>(out);
}

// round 15
// speedup vs baseline: 4.3327x; 1.0642x over previous
#include <cuda_runtime.h>
#include <cuda_fp16.h>
#include <cstdint>

#define NB 4
#define NT 1024
#define ND 512
#define NH 8
#define NHD 64
#define NHDIM 512   // NH*NHD
#define NM 4096     // NB*NT

// ---------------- scratch (static device arrays; no allocation) ----------------
__device__ float  g_q [NB*NH*NT*NHD];                // [b,h,t,d]   8 MB
__device__ float  g_k [NB*NH*NT*NHD];
__device__ __half g_vh[NB*NH*NT*NHD];                // V fp16, 4 MB
__device__ __half g_S [(size_t)NB*NH*NT*NT];         // raw scaled scores, fp16, 64 MB
__device__ __half g_Pf[(size_t)NB*NH*NT*NT];         // masked-normalized P (fwd), fp16
__device__ __half g_Pr[(size_t)NB*NH*NT*NT];         // masked-normalized P (rev), fp16
__device__ float  g_Tf[NM*NHDIM];                    // [b*t, h*64+d]  8 MB
__device__ float  g_Tr[NM*NHDIM];
__device__ float  g_FG[4*(size_t)NM*NHDIM];          // Ff|Gf|Fr|Gr pre-act, 32 MB

// ======================= mma helpers ================================
__device__ __forceinline__ uint32_t f2tf(float f){
    uint32_t r; asm("cvt.rna.tf32.f32 %0, %1;" : "=r"(r) : "f"(f)); return r;
}
__device__ __forceinline__ void mma_tf32(float* c, const uint32_t* a, const uint32_t* b){
    asm volatile("mma.sync.aligned.m16n8k8.row.col.f32.tf32.tf32.f32 "
        "{%0,%1,%2,%3}, {%4,%5,%6,%7}, {%8,%9}, {%0,%1,%2,%3};"
        : "+f"(c[0]), "+f"(c[1]), "+f"(c[2]), "+f"(c[3])
        : "r"(a[0]), "r"(a[1]), "r"(a[2]), "r"(a[3]), "r"(b[0]), "r"(b[1]));
}
__device__ __forceinline__ void mma_f16(float* c, const uint32_t* a, const uint32_t* b){
    asm volatile("mma.sync.aligned.m16n8k16.row.col.f32.f16.f16.f32 "
        "{%0,%1,%2,%3}, {%4,%5,%6,%7}, {%8,%9}, {%0,%1,%2,%3};"
        : "+f"(c[0]), "+f"(c[1]), "+f"(c[2]), "+f"(c[3])
        : "r"(a[0]), "r"(a[1]), "r"(a[2]), "r"(a[3]), "r"(b[0]), "r"(b[1]));
}

#define PA 36    // fp32 row pad: frag bank = 4g+t -> conflict-free
#define PB 136
#define PH 40    // fp16 row pad (halves): 16B-aligned rows + conflict-free frags

// Mainloop: acc[mi][ni][4] += A[m0+.., k] * W[k, n0+..]^T, K=512, both stride 512.
__device__ __forceinline__ void mma_mainloop(const float* __restrict__ A, int m0,
                                             const float* __restrict__ W, int n0,
                                             float (*sA)[PA], float (*sB)[PB],
                                             float acc[4][4][4],
                                             int tid, int g, int t, int wm, int wn)
{
    for (int c=0; c<16; c++){
#pragma unroll
        for (int i=0;i<4;i++){
            int f = i*256 + tid;
            int r = f>>3, c4 = f&7;
            float4 v = *(const float4*)&A[(size_t)(m0+r)*512 + c*32 + c4*4];
            uint32_t* pa = (uint32_t*)&sA[r][c4*4];
            pa[0]=f2tf(v.x); pa[1]=f2tf(v.y); pa[2]=f2tf(v.z); pa[3]=f2tf(v.w);
        }
#pragma unroll
        for (int i=0;i<4;i++){
            int f = i*256 + tid;
            int kl = f>>5, n4 = f&31;
            float4 v = *(const float4*)&W[(size_t)(c*32+kl)*512 + n0 + n4*4];
            uint32_t* pb = (uint32_t*)&sB[kl][n4*4];
            pb[0]=f2tf(v.x); pb[1]=f2tf(v.y); pb[2]=f2tf(v.z); pb[3]=f2tf(v.w);
        }
        __syncthreads();
#pragma unroll
        for (int kk=0; kk<4; kk++){
            const int k8 = kk*8;
            uint32_t afr[4][4];
#pragma unroll
            for (int mi=0; mi<4; mi++){
                int rb = wm*64 + mi*16;
                afr[mi][0] = __float_as_uint(sA[rb+g  ][k8+t  ]);
                afr[mi][1] = __float_as_uint(sA[rb+g+8][k8+t  ]);
                afr[mi][2] = __float_as_uint(sA[rb+g  ][k8+t+4]);
                afr[mi][3] = __float_as_uint(sA[rb+g+8][k8+t+4]);
            }
            uint32_t bfr[4][2];
#pragma unroll
            for (int ni=0; ni<4; ni++){
                int nb = wn*32 + ni*8 + g;
                bfr[ni][0] = __float_as_uint(sB[k8+t  ][nb]);
                bfr[ni][1] = __float_as_uint(sB[k8+t+4][nb]);
            }
#pragma unroll
            for (int mi=0; mi<4; mi++)
#pragma unroll
                for (int ni=0; ni<4; ni++)
                    mma_tf32(acc[mi][ni], afr[mi], bfr[ni]);
        }
        __syncthreads();
    }
}

// ---------------- K1: QKV projection, tf32 mma (V emitted fp16) ---------------
__global__ __launch_bounds__(256) void k_proj_mma(const float* __restrict__ X,
                                                  const float* __restrict__ Wq,
                                                  const float* __restrict__ bq,
                                                  const float* __restrict__ Wk,
                                                  const float* __restrict__ bk,
                                                  const float* __restrict__ Wv,
                                                  const float* __restrict__ bv)
{
    __shared__ float sA[128][PA];
    __shared__ float sB[32][PB];
    const int tid = threadIdx.x, lane = tid&31, warp = tid>>5;
    const int g = lane>>2, t = lane&3;
    const int wm = warp>>2, wn = warp&3;
    const int n0 = blockIdx.x*128, m0 = blockIdx.y*128;
    const int mat = n0>>9, col0 = n0&511;
    const float* W    = (mat==0)?Wq:(mat==1)?Wk:Wv;
    const float* bias = (mat==0)?bq:(mat==1)?bk:bv;

    float acc[4][4][4];
#pragma unroll
    for (int mi=0;mi<4;mi++)
#pragma unroll
        for (int ni=0;ni<4;ni++)
#pragma unroll
            for (int r=0;r<4;r++) acc[mi][ni][r]=0.f;

    mma_mainloop(X, m0, W, col0, sA, sB, acc, tid, g, t, wm, wn);

#pragma unroll
    for (int mi=0;mi<4;mi++){
#pragma unroll
        for (int ni=0;ni<4;ni++){
            int colb = col0 + wn*32 + ni*8 + 2*t;
            int h = colb>>6, d = colb&63;
            float b0v = bias[colb], b1v = bias[colb+1];
            int r0 = m0 + wm*64 + mi*16 + g;
#pragma unroll
            for (int half=0; half<2; half++){
                int m = r0 + half*8;
                int b = m>>10, tt = m&1023;
                float ox = acc[mi][ni][half*2+0] + b0v;
                float oy = acc[mi][ni][half*2+1] + b1v;
                size_t off = (((size_t)(b*NH+h))*NT + tt)*NHD + d;
                if (mat==0)      { float2 o; o.x=ox; o.y=oy; *(float2*)&g_q[off] = o; }
                else if (mat==1) { float2 o; o.x=ox; o.y=oy; *(float2*)&g_k[off] = o; }
                else             { *(__half2*)&g_vh[off] = __floats2half2_rn(ox, oy); }
            }
        }
    }
}

// ---------------- K5: four output GEMMs, tf32 mma -----------------------------
__global__ __launch_bounds__(256) void k_gemm4_mma(const float* __restrict__ Wfh, const float* __restrict__ bfh,
                                                   const float* __restrict__ Wfg, const float* __restrict__ bfg,
                                                   const float* __restrict__ Wrh, const float* __restrict__ brh,
                                                   const float* __restrict__ Wrg, const float* __restrict__ brg)
{
    __shared__ float sA[128][PA];
    __shared__ float sB[32][PB];
    const int tid = threadIdx.x, lane = tid&31, warp = tid>>5;
    const int g = lane>>2, t = lane&3;
    const int wm = warp>>2, wn = warp&3;
    const int n0 = blockIdx.x*128, m0 = blockIdx.y*128, mat = blockIdx.z;
    const float* A    = (mat<2)? g_Tf : g_Tr;
    const float* W    = (mat==0)?Wfh:(mat==1)?Wfg:(mat==2)?Wrh:Wrg;
    const float* bias = (mat==0)?bfh:(mat==1)?bfg:(mat==2)?brh:brg;
    float* C = g_FG + (size_t)mat*NM*NHDIM;

    float acc[4][4][4];
#pragma unroll
    for (int mi=0;mi<4;mi++)
#pragma unroll
        for (int ni=0;ni<4;ni++)
#pragma unroll
            for (int r=0;r<4;r++) acc[mi][ni][r]=0.f;

    mma_mainloop(A, m0, W, n0, sA, sB, acc, tid, g, t, wm, wn);

#pragma unroll
    for (int mi=0;mi<4;mi++){
#pragma unroll
        for (int ni=0;ni<4;ni++){
            int colb = n0 + wn*32 + ni*8 + 2*t;
            float b0v = bias[colb], b1v = bias[colb+1];
            int r0 = m0 + wm*64 + mi*16 + g;
#pragma unroll
            for (int half=0; half<2; half++){
                int m = r0 + half*8;
                float2 o;
                o.x = acc[mi][ni][half*2+0] + b0v;
                o.y = acc[mi][ni][half*2+1] + b1v;
                *(float2*)&C[(size_t)m*NHDIM + colb] = o;
            }
        }
    }
}

// ---------------- K2: scores via tf32 mma -> fp16 S ---------------------------
__global__ __launch_bounds__(256) void k_scores_mma()
{
    __shared__ float sQ[128][PA];
    __shared__ float sK[128][PA];
    const int tid = threadIdx.x, lane = tid&31, warp = tid>>5;
    const int g = lane>>2, t = lane&3;
    const int wm = warp>>2, wn = warp&3;
    const int k0 = blockIdx.x*128, q0 = blockIdx.y*128;
    const size_t bh = blockIdx.z;
    const float* Q  = g_q + (bh*NT + (size_t)q0)*NHD;
    const float* Kp = g_k + (bh*NT + (size_t)k0)*NHD;
    __half* S = g_S + bh*NT*NT + (size_t)q0*NT + k0;

    float acc[4][4][4];
#pragma unroll
    for (int mi=0;mi<4;mi++)
#pragma unroll
        for (int ni=0;ni<4;ni++)
#pragma unroll
            for (int r=0;r<4;r++) acc[mi][ni][r]=0.f;

#pragma unroll
    for (int c=0; c<2; c++){
#pragma unroll
        for (int i=0;i<4;i++){
            int f = i*256 + tid;
            int r = f>>3, c4 = f&7;
            float4 a = *(const float4*)&Q [(size_t)r*NHD + c*32 + c4*4];
            float4 b = *(const float4*)&Kp[(size_t)r*NHD + c*32 + c4*4];
            uint32_t* pq = (uint32_t*)&sQ[r][c4*4];
            pq[0]=f2tf(a.x*0.125f); pq[1]=f2tf(a.y*0.125f);
            pq[2]=f2tf(a.z*0.125f); pq[3]=f2tf(a.w*0.125f);
            uint32_t* pk = (uint32_t*)&sK[r][c4*4];
            pk[0]=f2tf(b.x); pk[1]=f2tf(b.y); pk[2]=f2tf(b.z); pk[3]=f2tf(b.w);
        }
        __syncthreads();
#pragma unroll
        for (int kk=0; kk<4; kk++){
            const int k8 = kk*8;
            uint32_t afr[4][4];
#pragma unroll
            for (int mi=0; mi<4; mi++){
                int rb = wm*64 + mi*16;
                afr[mi][0] = __float_as_uint(sQ[rb+g  ][k8+t  ]);
                afr[mi][1] = __float_as_uint(sQ[rb+g+8][k8+t  ]);
                afr[mi][2] = __float_as_uint(sQ[rb+g  ][k8+t+4]);
                afr[mi][3] = __float_as_uint(sQ[rb+g+8][k8+t+4]);
            }
            uint32_t bfr[4][2];
#pragma unroll
            for (int ni=0; ni<4; ni++){
                int nb = wn*32 + ni*8 + g;
                bfr[ni][0] = __float_as_uint(sK[nb][k8+t  ]);
                bfr[ni][1] = __float_as_uint(sK[nb][k8+t+4]);
            }
#pragma unroll
            for (int mi=0; mi<4; mi++)
#pragma unroll
                for (int ni=0; ni<4; ni++)
                    mma_tf32(acc[mi][ni], afr[mi], bfr[ni]);
        }
        __syncthreads();
    }
#pragma unroll
    for (int mi=0;mi<4;mi++){
#pragma unroll
        for (int ni=0;ni<4;ni++){
            int col = wn*32 + ni*8 + 2*t;
            int r0 = wm*64 + mi*16 + g;
#pragma unroll
            for (int half=0; half<2; half++){
                *(__half2*)&S[(size_t)(r0+half*8)*NT + col] =
                    __floats2half2_rn(acc[mi][ni][half*2+0], acc[mi][ni][half*2+1]);
            }
        }
    }
}

// ------------- K3: softmax + gate + masks -> fp16 Pf/Pr ----------------------
__global__ __launch_bounds__(256) void k_gate(const float* __restrict__ cw,
                                              const float* __restrict__ cbp)
{
    __shared__ float sS[8][1024];
    __shared__ float sInv[8];
    __shared__ float red[8][16];
    __shared__ float sIf[8], sIr[8];
    const int tid = threadIdx.x;
    const int q = blockIdx.x, b = blockIdx.y;
    const size_t base = ((size_t)(b*NH))*NT*NT + (size_t)q*NT;

    // load all 8 head-rows (fp16 -> fp32)
#pragma unroll
    for (int i=0;i<4;i++){
        int f = i*256 + tid;           // 0..1023
        int h = f>>7, j8 = (f&127)*8;
        uint4 v = *(const uint4*)&g_S[base + (size_t)h*NT*NT + j8];
        const __half2* hv = (const __half2*)&v;
        float2 f0=__half22float2(hv[0]), f1=__half22float2(hv[1]);
        float2 f2=__half22float2(hv[2]), f3=__half22float2(hv[3]);
        sS[h][j8+0]=f0.x; sS[h][j8+1]=f0.y; sS[h][j8+2]=f1.x; sS[h][j8+3]=f1.y;
        sS[h][j8+4]=f2.x; sS[h][j8+5]=f2.y; sS[h][j8+6]=f3.x; sS[h][j8+7]=f3.y;
    }
    __syncthreads();

    const int warp = tid>>5, lane = tid&31;
    {
        float m = -1e30f;
#pragma unroll
        for (int j=0;j<32;j++) m = fmaxf(m, sS[warp][lane + 32*j]);
#pragma unroll
        for (int off=16; off>0; off>>=1) m = fmaxf(m, __shfl_xor_sync(0xffffffffu, m, off));
        float sum = 0.f;
#pragma unroll
        for (int j=0;j<32;j++){
            float e = __expf(sS[warp][lane + 32*j] - m);
            sS[warp][lane + 32*j] = e;
            sum += e;
        }
#pragma unroll
        for (int off=16; off>0; off>>=1) sum += __shfl_xor_sync(0xffffffffu, sum, off);
        if (lane==0) sInv[warp] = 1.0f/sum;
    }
    __syncthreads();

    float w[NH];
#pragma unroll
    for (int h=0;h<NH;h++) w[h]=cw[h];
    const float cb = cbp[0];
    float inv[NH];
#pragma unroll
    for (int h=0;h<NH;h++) inv[h]=sInv[h];

    float denf[NH], denr[NH];
#pragma unroll
    for (int h=0;h<NH;h++){ denf[h]=0.f; denr[h]=0.f; }
    float linv[2][2];

    // pass 1: A_t, lin, E=exp(A_t) back into sS, masked denominators
#pragma unroll
    for (int kk=0; kk<2; kk++){
#pragma unroll
        for (int j=0; j<2; j++){
            int k = kk*512 + tid*2 + j;
            float A[NH];
            float lin = cb;
#pragma unroll
            for (int h=0;h<NH;h++){ A[h] = sS[h][k]*inv[h]; lin = fmaf(w[h], A[h], lin); }
            linv[kk][j] = lin;
            bool bf = (lin <= 0.f);
            bool br = (lin >= 0.f);
#pragma unroll
            for (int h=0;h<NH;h++){
                float E = __expf(A[h]);
                sS[h][k] = E;
                denf[h] += bf ? E : 1.0f;
                denr[h] += br ? E : 1.0f;
            }
        }
    }
    // block reduction of 16 values
#pragma unroll
    for (int v=0; v<16; v++){
        float val = (v<8)? denf[v] : denr[v-8];
#pragma unroll
        for (int off=16; off>0; off>>=1) val += __shfl_down_sync(0xffffffffu, val, off);
        if (lane==0) red[warp][v]=val;
    }
    __syncthreads();
    if (tid < 16){
        float s=0.f;
#pragma unroll
        for (int wp=0; wp<8; wp++) s += red[wp][tid];
        float is = 1.0f/s;
        if (tid < 8) sIf[tid] = is;
        else         sIr[tid-8] = is;
    }
    __syncthreads();

    // pass 2: emit fp16 Pf/Pr (coalesced half2 stores)
#pragma unroll
    for (int kk=0; kk<2; kk++){
        int k = kk*512 + tid*2;
        float lin0 = linv[kk][0], lin1 = linv[kk][1];
        bool bf0 = (lin0 <= 0.f), bf1 = (lin1 <= 0.f);
        bool br0 = (lin0 >= 0.f), br1 = (lin1 >= 0.f);
#pragma unroll
        for (int h=0;h<NH;h++){
            float E0 = sS[h][k], E1 = sS[h][k+1];
            float fi = sIf[h], ri = sIr[h];
            __half2 pf = __floats2half2_rn((bf0? E0 : 1.0f)*fi, (bf1? E1 : 1.0f)*fi);
            __half2 pr = __floats2half2_rn((br0? E0 : 1.0f)*ri, (br1? E1 : 1.0f)*ri);
            size_t o = base + (size_t)h*NT*NT + k;
            *(__half2*)&g_Pf[o] = pf;
            *(__half2*)&g_Pr[o] = pr;
        }
    }
}

// ------------- K4: PV fp16 mma, double-buffered pipeline ----------------------
__global__ __launch_bounds__(256) void k_pv_mma()
{
    __shared__ __half sA[2][256*PH];   // rows 0-127 Pf, 128-255 Pr
    __shared__ __half sB[64*PH];       // V^T [d][k]
    const int tid = threadIdx.x, lane = tid&31, warp = tid>>5;
    const int g = lane>>2, t = lane&3;
    const int wm = warp>>1, wn = warp&1;       // wm: 4x64 rows, wn: 2x32 d-cols
    const int qt=blockIdx.x, h=blockIdx.y, b=blockIdx.z;
    const int q0 = qt*128;
    const size_t bh = (size_t)(b*NH+h);
    const __half* Pf = g_Pf + (bh*NT + (size_t)q0)*NT;
    const __half* Pr = g_Pr + (bh*NT + (size_t)q0)*NT;
    const __half* Vh = g_vh + bh*NT*NHD;

    const int qq = tid>>2, k8 = tid&3;        // A-copy coords (2 rows per P mat)
    const int kl = tid>>3, d8 = tid&7;        // B-copy coords

    uint4 rA0, rA1, rA2, rA3, rB;
#define PV_LOAD(c) do { int k0c=(c)*32;                                          \
        rA0 = *(const uint4*)&Pf[(size_t)(qq    )*NT + k0c + k8*8];              \
        rA1 = *(const uint4*)&Pf[(size_t)(qq+64 )*NT + k0c + k8*8];              \
        rA2 = *(const uint4*)&Pr[(size_t)(qq    )*NT + k0c + k8*8];              \
        rA3 = *(const uint4*)&Pr[(size_t)(qq+64 )*NT + k0c + k8*8];              \
        rB  = *(const uint4*)&Vh[(size_t)(k0c+kl)*NHD + d8*8];                   \
    } while(0)
#define PV_STORE_A(bf) do { __half* Ap = sA[bf];                                 \
        *(uint4*)&Ap[(qq     )*PH + k8*8] = rA0;                                 \
        *(uint4*)&Ap[(qq + 64)*PH + k8*8] = rA1;                                 \
        *(uint4*)&Ap[(qq +128)*PH + k8*8] = rA2;                                 \
        *(uint4*)&Ap[(qq +192)*PH + k8*8] = rA3;                                 \
    } while(0)
#define PV_STORE_B() do { const __half* hh=(const __half*)&rB;                   \
        _Pragma("unroll")                                                        \
        for (int j=0;j<8;j++) sB[(d8*8+j)*PH + kl] = hh[j];                      \
    } while(0)

    float acc[4][4][4];
#pragma unroll
    for (int mi=0;mi<4;mi++)
#pragma unroll
        for (int ni=0;ni<4;ni++)
#pragma unroll
            for (int r=0;r<4;r++) acc[mi][ni][r]=0.f;

    PV_LOAD(0); PV_STORE_A(0); PV_STORE_B();
    __syncthreads();

    for (int c=0; c<32; c++){
        if (c<31) PV_LOAD(c+1);
        const __half* Ap = sA[c&1];
#pragma unroll
        for (int kk=0; kk<2; kk++){
            const int k16 = kk*16;
            uint32_t afr[4][4];
#pragma unroll
            for (int mi=0; mi<4; mi++){
                int rr = wm*64 + mi*16;
                afr[mi][0] = *(const uint32_t*)&Ap[(rr+g  )*PH + k16 + 2*t    ];
                afr[mi][1] = *(const uint32_t*)&Ap[(rr+g+8)*PH + k16 + 2*t    ];
                afr[mi][2] = *(const uint32_t*)&Ap[(rr+g  )*PH + k16 + 2*t + 8];
                afr[mi][3] = *(const uint32_t*)&Ap[(rr+g+8)*PH + k16 + 2*t + 8];
            }
            uint32_t bfr[4][2];
#pragma unroll
            for (int ni=0; ni<4; ni++){
                int nb = wn*32 + ni*8 + g;
                bfr[ni][0] = *(const uint32_t*)&sB[nb*PH + k16 + 2*t    ];
                bfr[ni][1] = *(const uint32_t*)&sB[nb*PH + k16 + 2*t + 8];
            }
#pragma unroll
            for (int mi=0; mi<4; mi++)
#pragma unroll
                for (int ni=0; ni<4; ni++)
                    mma_f16(acc[mi][ni], afr[mi], bfr[ni]);
        }
        if (c<31){
            PV_STORE_A((c+1)&1);      // other buffer: safe before sync
            __syncthreads();          // all warps done reading sB of chunk c
            PV_STORE_B();
            __syncthreads();          // new sB visible
        }
    }

    // epilogue: rows <128 -> g_Tf, rows >=128 -> g_Tr
#pragma unroll
    for (int mi=0;mi<4;mi++){
#pragma unroll
        for (int ni=0;ni<4;ni++){
            int col = wn*32 + ni*8 + 2*t;
            int r0 = wm*64 + mi*16 + g;
#pragma unroll
            for (int half=0; half<2; half++){
                int rr = r0 + half*8;
                float* dst = (rr < 128) ? g_Tf : g_Tr;
                int q = q0 + (rr & 127);
                float2 o;
                o.x = acc[mi][ni][half*2+0];
                o.y = acc[mi][ni][half*2+1];
                *(float2*)&dst[((size_t)b*NT + q)*NHDIM + h*NHD + col] = o;
            }
        }
    }
#undef PV_LOAD
#undef PV_STORE_A
#undef PV_STORE_B
}

// ------------- K6: elementwise gate fuse -------------------------------------
__global__ __launch_bounds__(256) void k_fuse(float* __restrict__ out)
{
    const size_t idx = ((size_t)blockIdx.x*256 + threadIdx.x)*4;
    const size_t n = (size_t)NM*NHDIM;
    float4 Ff = *(const float4*)&g_FG[0*n + idx];
    float4 Gf = *(const float4*)&g_FG[1*n + idx];
    float4 Fr = *(const float4*)&g_FG[2*n + idx];
    float4 Gr = *(const float4*)&g_FG[3*n + idx];
    float4 o;
    {
        float gf = 1.f/(1.f + __expf(-Gf.x)), gr = 1.f/(1.f + __expf(-Gr.x));
        float wv = 1.f/(1.f + __expf(-(gf - gr)));
        o.x = Ff.x*wv + Fr.x*(1.f - wv);
    }
    {
        float gf = 1.f/(1.f + __expf(-Gf.y)), gr = 1.f/(1.f + __expf(-Gr.y));
        float wv = 1.f/(1.f + __expf(-(gf - gr)));
        o.y = Ff.y*wv + Fr.y*(1.f - wv);
    }
    {
        float gf = 1.f/(1.f + __expf(-Gf.z)), gr = 1.f/(1.f + __expf(-Gr.z));
        float wv = 1.f/(1.f + __expf(-(gf - gr)));
        o.z = Ff.z*wv + Fr.z*(1.f - wv);
    }
    {
        float gf = 1.f/(1.f + __expf(-Gf.w)), gr = 1.f/(1.f + __expf(-Gr.w));
        float wv = 1.f/(1.f + __expf(-(gf - gr)));
        o.w = Ff.w*wv + Fr.w*(1.f - wv);
    }
    *(float4*)&out[idx] = o;
}

// -------------------------------- launch --------------------------------------
extern "C" void kernel_launch(void* const* d_in, const int* in_sizes, int n_in,
                              void* d_out, int out_size)
{
    const float* x   = (const float*)d_in[0];
    const float* Wq  = (const float*)d_in[1];
    const float* bq  = (const float*)d_in[2];
    const float* Wk  = (const float*)d_in[3];
    const float* bk  = (const float*)d_in[4];
    const float* Wv  = (const float*)d_in[5];
    const float* bv  = (const float*)d_in[6];
    const float* cw  = (const float*)d_in[7];
    const float* cb  = (const float*)d_in[8];
    const float* Wfh = (const float*)d_in[9];
    const float* bfh = (const float*)d_in[10];
    const float* Wfg = (const float*)d_in[11];
    const float* bfg = (const float*)d_in[12];
    const float* Wrh = (const float*)d_in[13];
    const float* brh = (const float*)d_in[14];
    const float* Wrg = (const float*)d_in[15];
    const float* brg = (const float*)d_in[16];
    float* out = (float*)d_out;

    k_proj_mma  <<<dim3(12, 32), 256>>>(x, Wq, bq, Wk, bk, Wv, bv);
    k_scores_mma<<<dim3(8, 8, 32), 256>>>();
    k_gate      <<<dim3(1024, 4), 256>>>(cw, cb);
    k_pv_mma    <<<dim3(8, 8, 4), 256>>>();
    k_gemm4_mma <<<dim3(4, 32, 4), 256>>>(Wfh, bfh, Wfg, bfg, Wrh, brh, Wrg, brg);
    k_fuse      <<<2048, 256>>>(out);
}